// round 2
// baseline (speedup 1.0000x reference)
#include <cuda_runtime.h>

#define N_NODES 100000
#define N_EDGES 3200000
#define F_IN    512
#define F_HID   256
#define N_CLASS 41

// ---------------- scratch (device globals; no allocation allowed) ----------
__device__ float g_h1[(size_t)N_NODES * F_HID];   // x @ W1
__device__ float g_a1[(size_t)N_NODES * F_HID];   // edge-aggregated layer 1
__device__ float g_h2[(size_t)N_NODES * N_CLASS]; // relu(a1) @ W2
__device__ float g_a2[(size_t)N_NODES * N_CLASS]; // edge-aggregated layer 2
__device__ int   g_deg[N_NODES];
__device__ float g_dinv[N_NODES];
__device__ int   g_is64;                          // edge dtype flag

// ---------------- edge dtype detection -------------------------------------
// Sample first 128 words under the int64 interpretation (bytes [0,1024) —
// in-bounds under both layouts). If all are valid node ids, data is int64;
// otherwise it is int32 (two packed indices per 64-bit word look huge).
__global__ void k_detect(const void* __restrict__ ei) {
    if (threadIdx.x == 0 && blockIdx.x == 0) {
        const long long* p = (const long long*)ei;
        int ok = 1;
        for (int e = 0; e < 128; e++) {
            long long v = p[e];
            if (v < 0 || v >= N_NODES) { ok = 0; break; }
        }
        g_is64 = ok;
    }
}

__device__ __forceinline__ void load_edge(const void* __restrict__ ei, int e,
                                          int is64, int& s, int& d) {
    if (is64) {
        const long long* p = (const long long*)ei;
        s = (int)p[e];
        d = (int)p[N_EDGES + e];
    } else {
        const int* p = (const int*)ei;
        s = p[e];
        d = p[N_EDGES + e];
    }
}

// ---------------- init: zero accumulators, deg=1 (self loop) ---------------
__global__ void k_init() {
    int i = blockIdx.x * blockDim.x + threadIdx.x;
    if (i < N_NODES * F_HID)   g_a1[i] = 0.f;
    if (i < N_NODES * N_CLASS) g_a2[i] = 0.f;
    if (i < N_NODES)           g_deg[i] = 1;
}

__global__ void k_count(const void* __restrict__ ei) {
    int e = blockIdx.x * blockDim.x + threadIdx.x;
    if (e >= N_EDGES) return;
    int s, d;
    load_edge(ei, e, g_is64, s, d);
    if ((unsigned)d < N_NODES) atomicAdd(&g_deg[d], 1);
}

__global__ void k_dinv() {
    int i = blockIdx.x * blockDim.x + threadIdx.x;
    if (i < N_NODES) g_dinv[i] = rsqrtf((float)g_deg[i]);
}

// ---------------- GEMM1: g_h1[100000,256] = x[100000,512] @ W1[512,256] ----
__global__ __launch_bounds__(256) void k_gemm1(const float* __restrict__ A,
                                               const float* __restrict__ B) {
    __shared__ __align__(16) float As[64][16];
    __shared__ __align__(16) float Bs[16][64];
    const int M = N_NODES, K = F_IN, N = F_HID;
    int tid = threadIdx.x;
    int bm = blockIdx.y * 64;
    int bn = blockIdx.x * 64;
    int tx = tid & 15, ty = tid >> 4;
    int ar = tid >> 2, ac = (tid & 3) * 4;   // A tile: 64 rows x 16 k
    int br = tid >> 4, bc = (tid & 15) * 4;  // B tile: 16 k x 64 cols
    bool arow_ok = (bm + ar) < M;
    const float* Aptr = A + (size_t)(bm + ar) * K + ac;
    const float* Bptr = B + (size_t)br * N + bn + bc;

    float acc[4][4] = {};
    for (int k0 = 0; k0 < K; k0 += 16) {
        float4 av = arow_ok ? *(const float4*)(Aptr + k0)
                            : make_float4(0.f, 0.f, 0.f, 0.f);
        *(float4*)&As[ar][ac] = av;
        *(float4*)&Bs[br][bc] = *(const float4*)(Bptr + (size_t)k0 * N);
        __syncthreads();
#pragma unroll
        for (int k = 0; k < 16; k++) {
            float4 b = *(float4*)&Bs[k][tx * 4];
            float a0 = As[ty * 4 + 0][k];
            float a1 = As[ty * 4 + 1][k];
            float a2 = As[ty * 4 + 2][k];
            float a3 = As[ty * 4 + 3][k];
            acc[0][0] += a0 * b.x; acc[0][1] += a0 * b.y; acc[0][2] += a0 * b.z; acc[0][3] += a0 * b.w;
            acc[1][0] += a1 * b.x; acc[1][1] += a1 * b.y; acc[1][2] += a1 * b.z; acc[1][3] += a1 * b.w;
            acc[2][0] += a2 * b.x; acc[2][1] += a2 * b.y; acc[2][2] += a2 * b.z; acc[2][3] += a2 * b.w;
            acc[3][0] += a3 * b.x; acc[3][1] += a3 * b.y; acc[3][2] += a3 * b.z; acc[3][3] += a3 * b.w;
        }
        __syncthreads();
    }
#pragma unroll
    for (int i = 0; i < 4; i++) {
        int row = bm + ty * 4 + i;
        if (row < M) {
            float4 v = make_float4(acc[i][0], acc[i][1], acc[i][2], acc[i][3]);
            *(float4*)(g_h1 + (size_t)row * N + bn + tx * 4) = v;
        }
    }
}

// ---------------- layer-1 aggregation: warp per edge, scatter-add ----------
__global__ __launch_bounds__(256) void k_agg1(const void* __restrict__ ei) {
    int w = (blockIdx.x * blockDim.x + threadIdx.x) >> 5;
    int lane = threadIdx.x & 31;
    if (w >= N_EDGES) return;
    int s, d;
    load_edge(ei, w, g_is64, s, d);
    if ((unsigned)s >= N_NODES || (unsigned)d >= N_NODES) return;
    float norm = g_dinv[s] * g_dinv[d];
    const float* hs = g_h1 + (size_t)s * F_HID;
    float* ad = g_a1 + (size_t)d * F_HID;
#pragma unroll
    for (int f = lane; f < F_HID; f += 32)
        atomicAdd(ad + f, norm * hs[f]);
}

// ---------------- self-loop + bias + relu (in place on g_a1) ---------------
__global__ void k_relu1(const float* __restrict__ b1) {
    int idx = blockIdx.x * blockDim.x + threadIdx.x;
    if (idx >= N_NODES * F_HID) return;
    int node = idx >> 8;       // /256
    int f    = idx & 255;
    float ds = g_dinv[node] * g_dinv[node];
    float v = g_a1[idx] + ds * g_h1[idx] + b1[f];
    g_a1[idx] = fmaxf(v, 0.f);
}

// ---------------- GEMM2: g_h2[100000,41] = g_a1[100000,256] @ W2[256,41] ---
__global__ __launch_bounds__(256) void k_gemm2(const float* __restrict__ B) {
    __shared__ __align__(16) float As[64][16];
    __shared__ __align__(16) float Bs[16][48];
    const int M = N_NODES, K = F_HID;
    int tid = threadIdx.x;
    int bm = blockIdx.x * 64;
    int tx = tid & 15, ty = tid >> 4;        // 16x16 threads; 4 rows x 3 cols each
    int ar = tid >> 2, ac = (tid & 3) * 4;
    bool arow_ok = (bm + ar) < M;
    const float* Aptr = g_a1 + (size_t)(bm + ar) * K + ac;

    float acc[4][3] = {};
    for (int k0 = 0; k0 < K; k0 += 16) {
        float4 av = arow_ok ? *(const float4*)(Aptr + k0)
                            : make_float4(0.f, 0.f, 0.f, 0.f);
        *(float4*)&As[ar][ac] = av;
        for (int t = tid; t < 16 * 48; t += 256) {
            int r = t / 48, c = t % 48;
            Bs[r][c] = (c < N_CLASS) ? B[(size_t)(k0 + r) * N_CLASS + c] : 0.f;
        }
        __syncthreads();
#pragma unroll
        for (int k = 0; k < 16; k++) {
            float b0 = Bs[k][tx * 3 + 0];
            float b1v = Bs[k][tx * 3 + 1];
            float b2v = Bs[k][tx * 3 + 2];
#pragma unroll
            for (int i = 0; i < 4; i++) {
                float a = As[ty * 4 + i][k];
                acc[i][0] += a * b0;
                acc[i][1] += a * b1v;
                acc[i][2] += a * b2v;
            }
        }
        __syncthreads();
    }
#pragma unroll
    for (int i = 0; i < 4; i++) {
        int row = bm + ty * 4 + i;
        if (row < M) {
#pragma unroll
            for (int j = 0; j < 3; j++) {
                int c = tx * 3 + j;
                if (c < N_CLASS)
                    g_h2[(size_t)row * N_CLASS + c] = acc[i][j];
            }
        }
    }
}

// ---------------- layer-2 aggregation: warp per edge ----------------------
__global__ __launch_bounds__(256) void k_agg2(const void* __restrict__ ei) {
    int w = (blockIdx.x * blockDim.x + threadIdx.x) >> 5;
    int lane = threadIdx.x & 31;
    if (w >= N_EDGES) return;
    int s, d;
    load_edge(ei, w, g_is64, s, d);
    if ((unsigned)s >= N_NODES || (unsigned)d >= N_NODES) return;
    float norm = g_dinv[s] * g_dinv[d];
    const float* hs = g_h2 + (size_t)s * N_CLASS;
    float* ad = g_a2 + (size_t)d * N_CLASS;
    if (lane < N_CLASS) atomicAdd(ad + lane, norm * hs[lane]);
    int lane2 = lane + 32;
    if (lane2 < N_CLASS) atomicAdd(ad + lane2, norm * hs[lane2]);
}

// ---------------- self-loop + bias + log_softmax --------------------------
__global__ __launch_bounds__(256) void k_final(const float* __restrict__ b2,
                                               float* __restrict__ out) {
    int w = (blockIdx.x * blockDim.x + threadIdx.x) >> 5;
    int lane = threadIdx.x & 31;
    if (w >= N_NODES) return;
    float ds = g_dinv[w] * g_dinv[w];
    size_t base = (size_t)w * N_CLASS;
    int c0 = lane, c1 = lane + 32;
    float v0 = -1e30f, v1 = -1e30f;
    if (c0 < N_CLASS) v0 = g_a2[base + c0] + ds * g_h2[base + c0] + b2[c0];
    if (c1 < N_CLASS) v1 = g_a2[base + c1] + ds * g_h2[base + c1] + b2[c1];
    float m = fmaxf(v0, v1);
#pragma unroll
    for (int o = 16; o; o >>= 1) m = fmaxf(m, __shfl_xor_sync(0xffffffffu, m, o));
    float e = 0.f;
    if (c0 < N_CLASS) e += expf(v0 - m);
    if (c1 < N_CLASS) e += expf(v1 - m);
#pragma unroll
    for (int o = 16; o; o >>= 1) e += __shfl_xor_sync(0xffffffffu, e, o);
    float ls = m + logf(e);
    if (c0 < N_CLASS) out[base + c0] = v0 - ls;
    if (c1 < N_CLASS) out[base + c1] = v1 - ls;
}

// ---------------------------------------------------------------------------
extern "C" void kernel_launch(void* const* d_in, const int* in_sizes, int n_in,
                              void* d_out, int out_size) {
    const float* x  = (const float*)d_in[0];
    const void*  ei = d_in[1];               // int32 (harness-converted) or int64
    const float* W1 = (const float*)d_in[2];
    const float* b1 = (const float*)d_in[3];
    const float* W2 = (const float*)d_in[4];
    const float* b2 = (const float*)d_in[5];
    float* out = (float*)d_out;

    k_detect<<<1, 32>>>(ei);
    k_init<<<(N_NODES * F_HID + 255) / 256, 256>>>();
    k_count<<<(N_EDGES + 255) / 256, 256>>>(ei);
    k_dinv<<<(N_NODES + 255) / 256, 256>>>();

    dim3 g1(F_HID / 64, (N_NODES + 63) / 64);
    k_gemm1<<<g1, 256>>>(x, W1);

    long long agg_threads = (long long)N_EDGES * 32;
    k_agg1<<<(unsigned)((agg_threads + 255) / 256), 256>>>(ei);

    k_relu1<<<(N_NODES * F_HID + 255) / 256, 256>>>(b1);

    k_gemm2<<<(N_NODES + 63) / 64, 256>>>(W2);

    k_agg2<<<(unsigned)((agg_threads + 255) / 256), 256>>>(ei);

    k_final<<<(N_NODES * 32 + 255) / 256, 256>>>(b2, out);
}

// round 3
// speedup vs baseline: 2.6344x; 2.6344x over previous
#include <cuda_runtime.h>

#define N_NODES 100000
#define N_EDGES 3200000
#define F_IN    512
#define F_HID   256
#define N_CLASS 41
#define SCAN_BLOCKS ((N_NODES + 255) / 256)   // 391

// ---------------- scratch (device globals; no allocation allowed) ----------
__device__ float g_h1[(size_t)N_NODES * F_HID];   // x @ W1
__device__ float g_a1[(size_t)N_NODES * F_HID];   // relu(agg1 + self + b1)
__device__ float g_h2[(size_t)N_NODES * N_CLASS]; // a1 @ W2
__device__ int   g_deg[N_NODES];
__device__ float g_dinv[N_NODES];
__device__ int   g_rowptr[N_NODES + 1];
__device__ int   g_cursor[N_NODES];
__device__ int   g_bsum[SCAN_BLOCKS];
__device__ int   g_bsumx[SCAN_BLOCKS];
__device__ int   g_csrc[N_EDGES];                 // CSR: src per edge slot
__device__ float g_cnorm[N_EDGES];                // CSR: norm per edge slot
__device__ int   g_is64;

// ---------------- edge dtype detection -------------------------------------
__global__ void k_detect(const void* __restrict__ ei) {
    if (threadIdx.x == 0 && blockIdx.x == 0) {
        const long long* p = (const long long*)ei;
        int ok = 1;
        for (int e = 0; e < 128; e++) {
            long long v = p[e];
            if (v < 0 || v >= N_NODES) { ok = 0; break; }
        }
        g_is64 = ok;
    }
}

__device__ __forceinline__ void load_edge(const void* __restrict__ ei, int e,
                                          int is64, int& s, int& d) {
    if (is64) {
        const long long* p = (const long long*)ei;
        s = (int)p[e];
        d = (int)p[N_EDGES + e];
    } else {
        const int* p = (const int*)ei;
        s = p[e];
        d = p[N_EDGES + e];
    }
}

// ---------------- degree ----------------------------------------------------
__global__ void k_deg_init() {
    int i = blockIdx.x * blockDim.x + threadIdx.x;
    if (i < N_NODES) g_deg[i] = 1;          // self loop
}

__global__ void k_count(const void* __restrict__ ei) {
    int e = blockIdx.x * blockDim.x + threadIdx.x;
    if (e >= N_EDGES) return;
    int s, d;
    load_edge(ei, e, g_is64, s, d);
    if ((unsigned)d < N_NODES) atomicAdd(&g_deg[d], 1);
}

__global__ void k_dinv() {
    int i = blockIdx.x * blockDim.x + threadIdx.x;
    if (i < N_NODES) g_dinv[i] = rsqrtf((float)g_deg[i]);
}

// ---------------- CSR build: 3-phase scan + fill ---------------------------
__global__ void k_scan1() {
    __shared__ int sh[256];
    int t = threadIdx.x;
    int i = blockIdx.x * 256 + t;
    int v = (i < N_NODES) ? (g_deg[i] - 1) : 0;
    sh[t] = v;
    __syncthreads();
#pragma unroll
    for (int off = 1; off < 256; off <<= 1) {
        int add = (t >= off) ? sh[t - off] : 0;
        __syncthreads();
        sh[t] += add;
        __syncthreads();
    }
    if (i < N_NODES) g_rowptr[i] = sh[t] - v;   // exclusive (intra-block)
    if (t == 255) g_bsum[blockIdx.x] = sh[t];
}

__global__ void k_scan2() {
    __shared__ int sh[512];
    int t = threadIdx.x;
    int v = (t < SCAN_BLOCKS) ? g_bsum[t] : 0;
    sh[t] = v;
    __syncthreads();
#pragma unroll
    for (int off = 1; off < 512; off <<= 1) {
        int add = (t >= off) ? sh[t - off] : 0;
        __syncthreads();
        sh[t] += add;
        __syncthreads();
    }
    if (t < SCAN_BLOCKS) g_bsumx[t] = sh[t] - v; // exclusive block offsets
}

__global__ void k_scan3() {
    int i = blockIdx.x * blockDim.x + threadIdx.x;
    if (i < N_NODES) {
        int r = g_rowptr[i] + g_bsumx[i >> 8];
        g_rowptr[i] = r;
        g_cursor[i] = r;
    }
    if (i == 0) g_rowptr[N_NODES] = 0;  // patched by k_fill_total
}

__global__ void k_fill_total() {
    // total real edges = sum cnt; with guards some edges may be dropped, but
    // rowptr[N] must equal last exclusive prefix + last cnt:
    if (threadIdx.x == 0 && blockIdx.x == 0)
        g_rowptr[N_NODES] = g_bsumx[SCAN_BLOCKS - 1] + g_bsum[SCAN_BLOCKS - 1];
}

__global__ void k_fill(const void* __restrict__ ei) {
    int e = blockIdx.x * blockDim.x + threadIdx.x;
    if (e >= N_EDGES) return;
    int s, d;
    load_edge(ei, e, g_is64, s, d);
    if ((unsigned)s >= N_NODES || (unsigned)d >= N_NODES) return;
    float nrm = g_dinv[s] * g_dinv[d];
    int pos = atomicAdd(&g_cursor[d], 1);
    g_csrc[pos] = s;
    g_cnorm[pos] = nrm;
}

// ---------------- GEMM1: g_h1[100000,256] = x[100000,512] @ W1[512,256] ----
// 128x128 tile, K-chunk 16, 8x8 per thread (256 threads).
__global__ __launch_bounds__(256) void k_gemm1(const float* __restrict__ A,
                                               const float* __restrict__ B) {
    __shared__ __align__(16) float As[16][128];  // [k][m]
    __shared__ __align__(16) float Bs[16][128];  // [k][n]
    const int M = N_NODES, K = F_IN, N = F_HID;
    int tid = threadIdx.x;
    int bm = blockIdx.y * 128;
    int bn = blockIdx.x * 128;
    int tx = tid & 15, ty = tid >> 4;

    int ar = tid >> 2;            // 0..63 (rows ar, ar+64)
    int ac = (tid & 3) * 4;       // k-offset 0..12
    int br = tid >> 5;            // 0..7  (k rows br, br+8)
    int bc = (tid & 31) * 4;      // col offset

    float acc[8][8] = {};
    for (int k0 = 0; k0 < K; k0 += 16) {
        // A tile
#pragma unroll
        for (int h = 0; h < 2; h++) {
            int row = bm + ar + h * 64;
            float4 a = (row < M) ? *(const float4*)(A + (size_t)row * K + k0 + ac)
                                 : make_float4(0.f, 0.f, 0.f, 0.f);
            As[ac + 0][ar + h * 64] = a.x;
            As[ac + 1][ar + h * 64] = a.y;
            As[ac + 2][ar + h * 64] = a.z;
            As[ac + 3][ar + h * 64] = a.w;
        }
        // B tile
#pragma unroll
        for (int h = 0; h < 2; h++) {
            int kr = br + h * 8;
            *(float4*)&Bs[kr][bc] = *(const float4*)(B + (size_t)(k0 + kr) * N + bn + bc);
        }
        __syncthreads();
#pragma unroll
        for (int k = 0; k < 16; k++) {
            float4 a0 = *(float4*)&As[k][ty * 4];
            float4 a1 = *(float4*)&As[k][ty * 4 + 64];
            float4 b0 = *(float4*)&Bs[k][tx * 4];
            float4 b1 = *(float4*)&Bs[k][tx * 4 + 64];
            float av[8] = {a0.x, a0.y, a0.z, a0.w, a1.x, a1.y, a1.z, a1.w};
            float bv[8] = {b0.x, b0.y, b0.z, b0.w, b1.x, b1.y, b1.z, b1.w};
#pragma unroll
            for (int i = 0; i < 8; i++)
#pragma unroll
                for (int j = 0; j < 8; j++)
                    acc[i][j] += av[i] * bv[j];
        }
        __syncthreads();
    }
#pragma unroll
    for (int i = 0; i < 8; i++) {
        int row = bm + ty * 4 + (i & 3) + (i >> 2) * 64;
        if (row < M) {
            float4 v0 = make_float4(acc[i][0], acc[i][1], acc[i][2], acc[i][3]);
            float4 v1 = make_float4(acc[i][4], acc[i][5], acc[i][6], acc[i][7]);
            *(float4*)(g_h1 + (size_t)row * N + bn + tx * 4) = v0;
            *(float4*)(g_h1 + (size_t)row * N + bn + tx * 4 + 64) = v1;
        }
    }
}

// ---------------- layer-1 aggregation: CSR gather, warp per node -----------
// Fuses self-loop, bias, relu. Writes g_a1.
__global__ __launch_bounds__(256) void k_agg1(const float* __restrict__ b1) {
    int node = (blockIdx.x * blockDim.x + threadIdx.x) >> 5;
    int lane = threadIdx.x & 31;
    if (node >= N_NODES) return;
    int beg = g_rowptr[node], end = g_rowptr[node + 1];

    const float4* h1v = (const float4*)g_h1;
    float4 acc0 = make_float4(0.f, 0.f, 0.f, 0.f);
    float4 acc1 = make_float4(0.f, 0.f, 0.f, 0.f);

    int e = beg;
    for (; e + 2 <= end; e += 2) {
        int s0 = g_csrc[e], s1 = g_csrc[e + 1];
        float n0 = g_cnorm[e], n1 = g_cnorm[e + 1];
        const float4* r0 = h1v + (size_t)s0 * (F_HID / 4) + lane * 2;
        const float4* r1 = h1v + (size_t)s1 * (F_HID / 4) + lane * 2;
        float4 v00 = r0[0], v01 = r0[1];
        float4 v10 = r1[0], v11 = r1[1];
        acc0.x += n0 * v00.x; acc0.y += n0 * v00.y; acc0.z += n0 * v00.z; acc0.w += n0 * v00.w;
        acc1.x += n0 * v01.x; acc1.y += n0 * v01.y; acc1.z += n0 * v01.z; acc1.w += n0 * v01.w;
        acc0.x += n1 * v10.x; acc0.y += n1 * v10.y; acc0.z += n1 * v10.z; acc0.w += n1 * v10.w;
        acc1.x += n1 * v11.x; acc1.y += n1 * v11.y; acc1.z += n1 * v11.z; acc1.w += n1 * v11.w;
    }
    if (e < end) {
        int s0 = g_csrc[e];
        float n0 = g_cnorm[e];
        const float4* r0 = h1v + (size_t)s0 * (F_HID / 4) + lane * 2;
        float4 v00 = r0[0], v01 = r0[1];
        acc0.x += n0 * v00.x; acc0.y += n0 * v00.y; acc0.z += n0 * v00.z; acc0.w += n0 * v00.w;
        acc1.x += n0 * v01.x; acc1.y += n0 * v01.y; acc1.z += n0 * v01.z; acc1.w += n0 * v01.w;
    }
    // self loop
    {
        float ds = g_dinv[node] * g_dinv[node];
        const float4* r = h1v + (size_t)node * (F_HID / 4) + lane * 2;
        float4 v0 = r[0], v1 = r[1];
        acc0.x += ds * v0.x; acc0.y += ds * v0.y; acc0.z += ds * v0.z; acc0.w += ds * v0.w;
        acc1.x += ds * v1.x; acc1.y += ds * v1.y; acc1.z += ds * v1.z; acc1.w += ds * v1.w;
    }
    // bias + relu + store
    const float4* bb = (const float4*)b1 + lane * 2;
    float4 bv0 = bb[0], bv1 = bb[1];
    acc0.x = fmaxf(acc0.x + bv0.x, 0.f); acc0.y = fmaxf(acc0.y + bv0.y, 0.f);
    acc0.z = fmaxf(acc0.z + bv0.z, 0.f); acc0.w = fmaxf(acc0.w + bv0.w, 0.f);
    acc1.x = fmaxf(acc1.x + bv1.x, 0.f); acc1.y = fmaxf(acc1.y + bv1.y, 0.f);
    acc1.z = fmaxf(acc1.z + bv1.z, 0.f); acc1.w = fmaxf(acc1.w + bv1.w, 0.f);
    float4* outp = (float4*)g_a1 + (size_t)node * (F_HID / 4) + lane * 2;
    outp[0] = acc0;
    outp[1] = acc1;
}

// ---------------- GEMM2: g_h2[100000,41] = g_a1[100000,256] @ W2[256,41] ---
__global__ __launch_bounds__(256) void k_gemm2(const float* __restrict__ B) {
    __shared__ __align__(16) float As[64][16];
    __shared__ __align__(16) float Bs[16][48];
    const int M = N_NODES, K = F_HID;
    int tid = threadIdx.x;
    int bm = blockIdx.x * 64;
    int tx = tid & 15, ty = tid >> 4;
    int ar = tid >> 2, ac = (tid & 3) * 4;
    bool arow_ok = (bm + ar) < M;
    const float* Aptr = g_a1 + (size_t)(bm + ar) * K + ac;

    float acc[4][3] = {};
    for (int k0 = 0; k0 < K; k0 += 16) {
        float4 av = arow_ok ? *(const float4*)(Aptr + k0)
                            : make_float4(0.f, 0.f, 0.f, 0.f);
        *(float4*)&As[ar][ac] = av;
        for (int t = tid; t < 16 * 48; t += 256) {
            int r = t / 48, c = t % 48;
            Bs[r][c] = (c < N_CLASS) ? B[(size_t)(k0 + r) * N_CLASS + c] : 0.f;
        }
        __syncthreads();
#pragma unroll
        for (int k = 0; k < 16; k++) {
            float b0 = Bs[k][tx * 3 + 0];
            float b1v = Bs[k][tx * 3 + 1];
            float b2v = Bs[k][tx * 3 + 2];
#pragma unroll
            for (int i = 0; i < 4; i++) {
                float a = As[ty * 4 + i][k];
                acc[i][0] += a * b0;
                acc[i][1] += a * b1v;
                acc[i][2] += a * b2v;
            }
        }
        __syncthreads();
    }
#pragma unroll
    for (int i = 0; i < 4; i++) {
        int row = bm + ty * 4 + i;
        if (row < M) {
#pragma unroll
            for (int j = 0; j < 3; j++) {
                int c = tx * 3 + j;
                if (c < N_CLASS)
                    g_h2[(size_t)row * N_CLASS + c] = acc[i][j];
            }
        }
    }
}

// ---------------- layer-2 aggregation + log_softmax: warp per node ---------
__global__ __launch_bounds__(256) void k_agg2final(const float* __restrict__ b2,
                                                   float* __restrict__ out) {
    int node = (blockIdx.x * blockDim.x + threadIdx.x) >> 5;
    int lane = threadIdx.x & 31;
    if (node >= N_NODES) return;
    int beg = g_rowptr[node], end = g_rowptr[node + 1];
    int c1 = lane + 32;
    bool has1 = c1 < N_CLASS;

    float acc0 = 0.f, acc1 = 0.f;
    for (int e = beg; e < end; e++) {
        int s = g_csrc[e];
        float nrm = g_cnorm[e];
        const float* hs = g_h2 + (size_t)s * N_CLASS;
        acc0 += nrm * hs[lane];
        if (has1) acc1 += nrm * hs[c1];
    }
    // self loop
    {
        float ds = g_dinv[node] * g_dinv[node];
        const float* hs = g_h2 + (size_t)node * N_CLASS;
        acc0 += ds * hs[lane];
        if (has1) acc1 += ds * hs[c1];
    }
    float v0 = (lane < N_CLASS) ? acc0 + b2[lane] : -1e30f;
    float v1 = has1 ? acc1 + b2[c1] : -1e30f;
    float m = fmaxf(v0, v1);
#pragma unroll
    for (int o = 16; o; o >>= 1) m = fmaxf(m, __shfl_xor_sync(0xffffffffu, m, o));
    float e2 = 0.f;
    if (lane < N_CLASS) e2 += expf(v0 - m);
    if (has1) e2 += expf(v1 - m);
#pragma unroll
    for (int o = 16; o; o >>= 1) e2 += __shfl_xor_sync(0xffffffffu, e2, o);
    float ls = m + logf(e2);
    size_t base = (size_t)node * N_CLASS;
    if (lane < N_CLASS) out[base + lane] = v0 - ls;
    if (has1) out[base + c1] = v1 - ls;
}

// ---------------------------------------------------------------------------
extern "C" void kernel_launch(void* const* d_in, const int* in_sizes, int n_in,
                              void* d_out, int out_size) {
    const float* x  = (const float*)d_in[0];
    const void*  ei = d_in[1];
    const float* W1 = (const float*)d_in[2];
    const float* b1 = (const float*)d_in[3];
    const float* W2 = (const float*)d_in[4];
    const float* b2 = (const float*)d_in[5];
    float* out = (float*)d_out;

    k_detect<<<1, 32>>>(ei);
    k_deg_init<<<(N_NODES + 255) / 256, 256>>>();
    k_count<<<(N_EDGES + 255) / 256, 256>>>(ei);
    k_dinv<<<(N_NODES + 255) / 256, 256>>>();

    // CSR build
    k_scan1<<<SCAN_BLOCKS, 256>>>();
    k_scan2<<<1, 512>>>();
    k_scan3<<<(N_NODES + 255) / 256, 256>>>();
    k_fill_total<<<1, 32>>>();
    k_fill<<<(N_EDGES + 255) / 256, 256>>>(ei);

    // GEMM1 (can overlap CSR build only via stream tricks; keep serial)
    dim3 g1((F_HID + 127) / 128, (N_NODES + 127) / 128);
    k_gemm1<<<g1, 256>>>(x, W1);

    // layer-1 aggregation (fused self+bias+relu)
    k_agg1<<<(N_NODES * 32 + 255) / 256, 256>>>(b1);

    k_gemm2<<<(N_NODES + 63) / 64, 256>>>(W2);

    // layer-2 aggregation + log_softmax
    k_agg2final<<<(N_NODES * 32 + 255) / 256, 256>>>(b2, out);
}

// round 4
// speedup vs baseline: 6.0097x; 2.2813x over previous
#include <cuda_runtime.h>
#include <cuda_bf16.h>

#define N_NODES 100000
#define N_EDGES 3200000
#define F_IN    512
#define F_HID   256
#define N_CLASS 41
#define SCAN_BLOCKS ((N_NODES + 255) / 256)   // 391
#define AK 40   // smem k-stride in bf16 halves (32 data + 8 pad)

// ---------------- scratch (device globals; no allocation allowed) ----------
__device__ __nv_bfloat16 g_xb [(size_t)N_NODES * F_IN];    // x in bf16
__device__ __nv_bfloat16 g_w1t[(size_t)F_HID * F_IN];      // W1^T [n][k] bf16
__device__ __nv_bfloat16 g_w2t[(size_t)64 * F_HID];        // W2^T padded [64][256]
__device__ __nv_bfloat16 g_h1b[(size_t)N_NODES * F_HID];   // x@W1 bf16
__device__ __nv_bfloat16 g_a1b[(size_t)N_NODES * F_HID];   // relu(agg+self+b1) bf16
__device__ float g_h2[(size_t)N_NODES * N_CLASS];          // a1 @ W2 (fp32)
__device__ int   g_deg[N_NODES];
__device__ float g_dinv[N_NODES];
__device__ int   g_rowptr[N_NODES + 1];
__device__ int   g_cursor[N_NODES];
__device__ int   g_bsum[SCAN_BLOCKS];
__device__ int   g_bsumx[SCAN_BLOCKS];
__device__ int   g_csrc[N_EDGES];
__device__ float g_cnorm[N_EDGES];
__device__ int   g_is64;

// ---------------- small helpers --------------------------------------------
__device__ __forceinline__ void cp16(void* s, const void* g) {
    unsigned sa = (unsigned)__cvta_generic_to_shared(s);
    asm volatile("cp.async.cg.shared.global [%0],[%1],16;" :: "r"(sa), "l"(g));
}
__device__ __forceinline__ void cp16z(void* s, const void* g, bool pred) {
    unsigned sa = (unsigned)__cvta_generic_to_shared(s);
    int sz = pred ? 16 : 0;
    asm volatile("cp.async.cg.shared.global [%0],[%1],16,%2;" :: "r"(sa), "l"(g), "r"(sz));
}
#define CP_COMMIT() asm volatile("cp.async.commit_group;")

__device__ __forceinline__ void mma16816(float c[4], const unsigned a[4],
                                         unsigned b0, unsigned b1) {
    asm volatile(
        "mma.sync.aligned.m16n8k16.row.col.f32.bf16.bf16.f32 "
        "{%0,%1,%2,%3},{%4,%5,%6,%7},{%8,%9},{%0,%1,%2,%3};"
        : "+f"(c[0]), "+f"(c[1]), "+f"(c[2]), "+f"(c[3])
        : "r"(a[0]), "r"(a[1]), "r"(a[2]), "r"(a[3]), "r"(b0), "r"(b1));
}

// ---------------- edge dtype detection -------------------------------------
__global__ void k_detect(const void* __restrict__ ei) {
    if (threadIdx.x == 0 && blockIdx.x == 0) {
        const long long* p = (const long long*)ei;
        int ok = 1;
        for (int e = 0; e < 128; e++) {
            long long v = p[e];
            if (v < 0 || v >= N_NODES) { ok = 0; break; }
        }
        g_is64 = ok;
    }
}

__device__ __forceinline__ void load_edge(const void* __restrict__ ei, int e,
                                          int is64, int& s, int& d) {
    if (is64) {
        const long long* p = (const long long*)ei;
        s = (int)p[e];
        d = (int)p[N_EDGES + e];
    } else {
        const int* p = (const int*)ei;
        s = p[e];
        d = p[N_EDGES + e];
    }
}

// ---------------- degree / dinv --------------------------------------------
__global__ void k_deg_init() {
    int i = blockIdx.x * blockDim.x + threadIdx.x;
    if (i < N_NODES) g_deg[i] = 1;
}
__global__ void k_count(const void* __restrict__ ei) {
    int e = blockIdx.x * blockDim.x + threadIdx.x;
    if (e >= N_EDGES) return;
    int s, d;
    load_edge(ei, e, g_is64, s, d);
    if ((unsigned)d < N_NODES) atomicAdd(&g_deg[d], 1);
}
__global__ void k_dinv() {
    int i = blockIdx.x * blockDim.x + threadIdx.x;
    if (i < N_NODES) g_dinv[i] = rsqrtf((float)g_deg[i]);
}

// ---------------- CSR build -------------------------------------------------
__global__ void k_scan1() {
    __shared__ int sh[256];
    int t = threadIdx.x;
    int i = blockIdx.x * 256 + t;
    int v = (i < N_NODES) ? (g_deg[i] - 1) : 0;
    sh[t] = v;
    __syncthreads();
#pragma unroll
    for (int off = 1; off < 256; off <<= 1) {
        int add = (t >= off) ? sh[t - off] : 0;
        __syncthreads();
        sh[t] += add;
        __syncthreads();
    }
    if (i < N_NODES) g_rowptr[i] = sh[t] - v;
    if (t == 255) g_bsum[blockIdx.x] = sh[t];
}
__global__ void k_scan2() {
    __shared__ int sh[512];
    int t = threadIdx.x;
    int v = (t < SCAN_BLOCKS) ? g_bsum[t] : 0;
    sh[t] = v;
    __syncthreads();
#pragma unroll
    for (int off = 1; off < 512; off <<= 1) {
        int add = (t >= off) ? sh[t - off] : 0;
        __syncthreads();
        sh[t] += add;
        __syncthreads();
    }
    if (t < SCAN_BLOCKS) g_bsumx[t] = sh[t] - v;
}
__global__ void k_scan3() {
    int i = blockIdx.x * blockDim.x + threadIdx.x;
    if (i < N_NODES) {
        int r = g_rowptr[i] + g_bsumx[i >> 8];
        g_rowptr[i] = r;
        g_cursor[i] = r;
    }
}
__global__ void k_fill_total() {
    if (threadIdx.x == 0 && blockIdx.x == 0)
        g_rowptr[N_NODES] = g_bsumx[SCAN_BLOCKS - 1] + g_bsum[SCAN_BLOCKS - 1];
}
__global__ void k_fill(const void* __restrict__ ei) {
    int e = blockIdx.x * blockDim.x + threadIdx.x;
    if (e >= N_EDGES) return;
    int s, d;
    load_edge(ei, e, g_is64, s, d);
    if ((unsigned)s >= N_NODES || (unsigned)d >= N_NODES) return;
    float nrm = g_dinv[s] * g_dinv[d];
    int pos = atomicAdd(&g_cursor[d], 1);
    g_csrc[pos] = s;
    g_cnorm[pos] = nrm;
}

// ---------------- conversions ----------------------------------------------
__global__ void k_xtobf16(const float* __restrict__ x) {
    size_t i = ((size_t)blockIdx.x * blockDim.x + threadIdx.x) * 8;
    if (i >= (size_t)N_NODES * F_IN) return;
    float4 v0 = *(const float4*)(x + i);
    float4 v1 = *(const float4*)(x + i + 4);
    __nv_bfloat162 p[4];
    p[0] = __floats2bfloat162_rn(v0.x, v0.y);
    p[1] = __floats2bfloat162_rn(v0.z, v0.w);
    p[2] = __floats2bfloat162_rn(v1.x, v1.y);
    p[3] = __floats2bfloat162_rn(v1.z, v1.w);
    *(uint4*)(g_xb + i) = *(uint4*)p;
}
__global__ void k_w1t(const float* __restrict__ W1) {
    int id = blockIdx.x * blockDim.x + threadIdx.x;   // 512*256
    if (id >= F_IN * F_HID) return;
    int n = id & (F_HID - 1), k = id >> 8;
    g_w1t[(size_t)n * F_IN + k] = __float2bfloat16(W1[(size_t)k * F_HID + n]);
}
__global__ void k_w2t(const float* __restrict__ W2) {
    int id = blockIdx.x * blockDim.x + threadIdx.x;   // 64*256
    if (id >= 64 * F_HID) return;
    int n = id & 63, k = id >> 6;
    float v = (n < N_CLASS) ? W2[(size_t)k * N_CLASS + n] : 0.f;
    g_w2t[(size_t)n * F_HID + k] = __float2bfloat16(v);
}

// ---------------- GEMM1: h1b = xb @ W1 (bf16 mma, 128x128 tile) ------------
__global__ __launch_bounds__(256) void k_gemm1t() {
    __shared__ __align__(16) __nv_bfloat16 As[2][128 * AK];
    __shared__ __align__(16) __nv_bfloat16 Bs[2][128 * AK];
    int tid = threadIdx.x;
    int bm = blockIdx.y * 128, bn = blockIdx.x * 128;
    int wid = tid >> 5, lane = tid & 31;
    int wm = (wid & 3) * 32, wn = (wid >> 2) * 64;
    int g = lane >> 2, tg = lane & 3;

    float acc[2][8][4] = {};

#define G1_ISSUE(buf, k0)                                                     \
    {                                                                         \
        _Pragma("unroll")                                                     \
        for (int h = 0; h < 2; h++) {                                         \
            int id = tid + h * 256;                                           \
            int row = id >> 2, kg = id & 3;                                   \
            int ar = bm + row;                                                \
            bool ok = ar < N_NODES;                                           \
            const void* ga = g_xb + (size_t)(ok ? ar : 0) * F_IN + (k0) + kg * 8; \
            cp16z(&As[buf][row * AK + kg * 8], ga, ok);                       \
            const void* gb = g_w1t + (size_t)(bn + row) * F_IN + (k0) + kg * 8; \
            cp16(&Bs[buf][row * AK + kg * 8], gb);                            \
        }                                                                     \
        CP_COMMIT();                                                          \
    }

    G1_ISSUE(0, 0)
    const int nchunk = F_IN / 32;   // 16
    for (int c = 0; c < nchunk; c++) {
        if (c + 1 < nchunk) {
            G1_ISSUE((c + 1) & 1, (c + 1) * 32)
            asm volatile("cp.async.wait_group 1;");
        } else {
            asm volatile("cp.async.wait_group 0;");
        }
        __syncthreads();
        const __nv_bfloat16* A = As[c & 1];
        const __nv_bfloat16* B = Bs[c & 1];
#pragma unroll
        for (int kk = 0; kk < 32; kk += 16) {
            unsigned a[2][4];
#pragma unroll
            for (int mt = 0; mt < 2; mt++) {
                int r = wm + mt * 16 + g;
                a[mt][0] = *(const unsigned*)&A[r * AK + kk + 2 * tg];
                a[mt][1] = *(const unsigned*)&A[(r + 8) * AK + kk + 2 * tg];
                a[mt][2] = *(const unsigned*)&A[r * AK + kk + 2 * tg + 8];
                a[mt][3] = *(const unsigned*)&A[(r + 8) * AK + kk + 2 * tg + 8];
            }
#pragma unroll
            for (int nt = 0; nt < 8; nt++) {
                int n = wn + nt * 8 + g;
                unsigned b0 = *(const unsigned*)&B[n * AK + kk + 2 * tg];
                unsigned b1 = *(const unsigned*)&B[n * AK + kk + 2 * tg + 8];
                mma16816(acc[0][nt], a[0], b0, b1);
                mma16816(acc[1][nt], a[1], b0, b1);
            }
        }
        __syncthreads();
    }
#pragma unroll
    for (int mt = 0; mt < 2; mt++) {
        int r0 = bm + wm + mt * 16 + g;
#pragma unroll
        for (int nt = 0; nt < 8; nt++) {
            int c0 = bn + wn + nt * 8 + 2 * tg;
            if (r0 < N_NODES) {
                __nv_bfloat162 p = __floats2bfloat162_rn(acc[mt][nt][0], acc[mt][nt][1]);
                *(__nv_bfloat162*)&g_h1b[(size_t)r0 * F_HID + c0] = p;
            }
            if (r0 + 8 < N_NODES) {
                __nv_bfloat162 p = __floats2bfloat162_rn(acc[mt][nt][2], acc[mt][nt][3]);
                *(__nv_bfloat162*)&g_h1b[(size_t)(r0 + 8) * F_HID + c0] = p;
            }
        }
    }
}

// ---------------- layer-1 aggregation: CSR gather on bf16 ------------------
__device__ __forceinline__ void acc8(float* acc, uint4 v, float nrm) {
    __nv_bfloat162* h = (__nv_bfloat162*)&v;
    float2 f0 = __bfloat1622float2(h[0]);
    float2 f1 = __bfloat1622float2(h[1]);
    float2 f2 = __bfloat1622float2(h[2]);
    float2 f3 = __bfloat1622float2(h[3]);
    acc[0] += nrm * f0.x; acc[1] += nrm * f0.y;
    acc[2] += nrm * f1.x; acc[3] += nrm * f1.y;
    acc[4] += nrm * f2.x; acc[5] += nrm * f2.y;
    acc[6] += nrm * f3.x; acc[7] += nrm * f3.y;
}

__global__ __launch_bounds__(256) void k_agg1(const float* __restrict__ b1) {
    int node = (blockIdx.x * blockDim.x + threadIdx.x) >> 5;
    int lane = threadIdx.x & 31;
    if (node >= N_NODES) return;
    int beg = g_rowptr[node], end = g_rowptr[node + 1];
    const uint4* hb = (const uint4*)g_h1b;   // 32 uint4 per row

    float acc[8] = {};
    int e = beg;
    for (; e + 2 <= end; e += 2) {
        int s0 = g_csrc[e], s1 = g_csrc[e + 1];
        float n0 = g_cnorm[e], n1 = g_cnorm[e + 1];
        uint4 v0 = hb[(size_t)s0 * 32 + lane];
        uint4 v1 = hb[(size_t)s1 * 32 + lane];
        acc8(acc, v0, n0);
        acc8(acc, v1, n1);
    }
    if (e < end) {
        uint4 v = hb[(size_t)g_csrc[e] * 32 + lane];
        acc8(acc, v, g_cnorm[e]);
    }
    {   // self loop
        float ds = g_dinv[node] * g_dinv[node];
        uint4 v = hb[(size_t)node * 32 + lane];
        acc8(acc, v, ds);
    }
    // bias + relu -> bf16 store
    float4 bv0 = *((const float4*)b1 + lane * 2);
    float4 bv1 = *((const float4*)b1 + lane * 2 + 1);
    float r[8];
    r[0] = fmaxf(acc[0] + bv0.x, 0.f); r[1] = fmaxf(acc[1] + bv0.y, 0.f);
    r[2] = fmaxf(acc[2] + bv0.z, 0.f); r[3] = fmaxf(acc[3] + bv0.w, 0.f);
    r[4] = fmaxf(acc[4] + bv1.x, 0.f); r[5] = fmaxf(acc[5] + bv1.y, 0.f);
    r[6] = fmaxf(acc[6] + bv1.z, 0.f); r[7] = fmaxf(acc[7] + bv1.w, 0.f);
    __nv_bfloat162 p[4];
    p[0] = __floats2bfloat162_rn(r[0], r[1]);
    p[1] = __floats2bfloat162_rn(r[2], r[3]);
    p[2] = __floats2bfloat162_rn(r[4], r[5]);
    p[3] = __floats2bfloat162_rn(r[6], r[7]);
    ((uint4*)g_a1b)[(size_t)node * 32 + lane] = *(uint4*)p;
}

// ---------------- GEMM2: h2 = a1b @ W2 (bf16 mma, 128x64 tile) -------------
__global__ __launch_bounds__(256) void k_gemm2t() {
    __shared__ __align__(16) __nv_bfloat16 As[2][128 * AK];
    __shared__ __align__(16) __nv_bfloat16 Bs[2][64 * AK];
    int tid = threadIdx.x;
    int bm = blockIdx.x * 128;
    int wid = tid >> 5, lane = tid & 31;
    int wm = (wid & 3) * 32, wn = (wid >> 2) * 32;
    int g = lane >> 2, tg = lane & 3;

    float acc[2][4][4] = {};

#define G2_ISSUE(buf, k0)                                                     \
    {                                                                         \
        _Pragma("unroll")                                                     \
        for (int h = 0; h < 2; h++) {                                         \
            int id = tid + h * 256;                                           \
            int row = id >> 2, kg = id & 3;                                   \
            int ar = bm + row;                                                \
            bool ok = ar < N_NODES;                                           \
            const void* ga = g_a1b + (size_t)(ok ? ar : 0) * F_HID + (k0) + kg * 8; \
            cp16z(&As[buf][row * AK + kg * 8], ga, ok);                       \
        }                                                                     \
        {                                                                     \
            int row = tid >> 2, kg = tid & 3;                                 \
            if (row < 64) {                                                   \
                const void* gb = g_w2t + (size_t)row * F_HID + (k0) + kg * 8; \
                cp16(&Bs[buf][row * AK + kg * 8], gb);                        \
            }                                                                 \
        }                                                                     \
        CP_COMMIT();                                                          \
    }

    G2_ISSUE(0, 0)
    const int nchunk = F_HID / 32;   // 8
    for (int c = 0; c < nchunk; c++) {
        if (c + 1 < nchunk) {
            G2_ISSUE((c + 1) & 1, (c + 1) * 32)
            asm volatile("cp.async.wait_group 1;");
        } else {
            asm volatile("cp.async.wait_group 0;");
        }
        __syncthreads();
        const __nv_bfloat16* A = As[c & 1];
        const __nv_bfloat16* B = Bs[c & 1];
#pragma unroll
        for (int kk = 0; kk < 32; kk += 16) {
            unsigned a[2][4];
#pragma unroll
            for (int mt = 0; mt < 2; mt++) {
                int r = wm + mt * 16 + g;
                a[mt][0] = *(const unsigned*)&A[r * AK + kk + 2 * tg];
                a[mt][1] = *(const unsigned*)&A[(r + 8) * AK + kk + 2 * tg];
                a[mt][2] = *(const unsigned*)&A[r * AK + kk + 2 * tg + 8];
                a[mt][3] = *(const unsigned*)&A[(r + 8) * AK + kk + 2 * tg + 8];
            }
#pragma unroll
            for (int nt = 0; nt < 4; nt++) {
                int n = wn + nt * 8 + g;
                unsigned b0 = *(const unsigned*)&B[n * AK + kk + 2 * tg];
                unsigned b1 = *(const unsigned*)&B[n * AK + kk + 2 * tg + 8];
                mma16816(acc[0][nt], a[0], b0, b1);
                mma16816(acc[1][nt], a[1], b0, b1);
            }
        }
        __syncthreads();
    }
#pragma unroll
    for (int mt = 0; mt < 2; mt++) {
        int r0 = bm + wm + mt * 16 + g;
#pragma unroll
        for (int nt = 0; nt < 4; nt++) {
            int c0 = wn + nt * 8 + 2 * tg;
            if (r0 < N_NODES) {
                if (c0 < N_CLASS)     g_h2[(size_t)r0 * N_CLASS + c0]     = acc[mt][nt][0];
                if (c0 + 1 < N_CLASS) g_h2[(size_t)r0 * N_CLASS + c0 + 1] = acc[mt][nt][1];
            }
            if (r0 + 8 < N_NODES) {
                if (c0 < N_CLASS)     g_h2[(size_t)(r0 + 8) * N_CLASS + c0]     = acc[mt][nt][2];
                if (c0 + 1 < N_CLASS) g_h2[(size_t)(r0 + 8) * N_CLASS + c0 + 1] = acc[mt][nt][3];
            }
        }
    }
}

// ---------------- layer-2 aggregation + log_softmax ------------------------
__global__ __launch_bounds__(256) void k_agg2final(const float* __restrict__ b2,
                                                   float* __restrict__ out) {
    int node = (blockIdx.x * blockDim.x + threadIdx.x) >> 5;
    int lane = threadIdx.x & 31;
    if (node >= N_NODES) return;
    int beg = g_rowptr[node], end = g_rowptr[node + 1];
    int c1 = lane + 32;
    bool has1 = c1 < N_CLASS;

    float acc0 = 0.f, acc1 = 0.f;
    for (int e = beg; e < end; e++) {
        int s = g_csrc[e];
        float nrm = g_cnorm[e];
        const float* hs = g_h2 + (size_t)s * N_CLASS;
        acc0 += nrm * hs[lane];
        if (has1) acc1 += nrm * hs[c1];
    }
    {
        float ds = g_dinv[node] * g_dinv[node];
        const float* hs = g_h2 + (size_t)node * N_CLASS;
        acc0 += ds * hs[lane];
        if (has1) acc1 += ds * hs[c1];
    }
    float v0 = (lane < N_CLASS) ? acc0 + b2[lane] : -1e30f;
    float v1 = has1 ? acc1 + b2[c1] : -1e30f;
    float m = fmaxf(v0, v1);
#pragma unroll
    for (int o = 16; o; o >>= 1) m = fmaxf(m, __shfl_xor_sync(0xffffffffu, m, o));
    float e2 = 0.f;
    if (lane < N_CLASS) e2 += expf(v0 - m);
    if (has1) e2 += expf(v1 - m);
#pragma unroll
    for (int o = 16; o; o >>= 1) e2 += __shfl_xor_sync(0xffffffffu, e2, o);
    float ls = m + logf(e2);
    size_t base = (size_t)node * N_CLASS;
    if (lane < N_CLASS) out[base + lane] = v0 - ls;
    if (has1) out[base + c1] = v1 - ls;
}

// ---------------------------------------------------------------------------
extern "C" void kernel_launch(void* const* d_in, const int* in_sizes, int n_in,
                              void* d_out, int out_size) {
    const float* x  = (const float*)d_in[0];
    const void*  ei = d_in[1];
    const float* W1 = (const float*)d_in[2];
    const float* b1 = (const float*)d_in[3];
    const float* W2 = (const float*)d_in[4];
    const float* b2 = (const float*)d_in[5];
    float* out = (float*)d_out;

    k_detect<<<1, 32>>>(ei);
    k_deg_init<<<(N_NODES + 255) / 256, 256>>>();
    k_count<<<(N_EDGES + 255) / 256, 256>>>(ei);
    k_dinv<<<(N_NODES + 255) / 256, 256>>>();

    k_scan1<<<SCAN_BLOCKS, 256>>>();
    k_scan2<<<1, 512>>>();
    k_scan3<<<(N_NODES + 255) / 256, 256>>>();
    k_fill_total<<<1, 32>>>();
    k_fill<<<(N_EDGES + 255) / 256, 256>>>(ei);

    // bf16 conversions
    k_xtobf16<<<(int)(((size_t)N_NODES * F_IN / 8 + 255) / 256), 256>>>(x);
    k_w1t<<<(F_IN * F_HID + 255) / 256, 256>>>(W1);
    k_w2t<<<(64 * F_HID + 255) / 256, 256>>>(W2);

    dim3 g1(F_HID / 128, (N_NODES + 127) / 128);   // (2, 782)
    k_gemm1t<<<g1, 256>>>();

    k_agg1<<<(N_NODES * 32 + 255) / 256, 256>>>(b1);

    k_gemm2t<<<(N_NODES + 127) / 128, 256>>>();

    k_agg2final<<<(N_NODES * 32 + 255) / 256, 256>>>(b2, out);
}

// round 5
// speedup vs baseline: 6.3444x; 1.0557x over previous
#include <cuda_runtime.h>
#include <cuda_bf16.h>

#define N_NODES 100000
#define N_EDGES 3200000
#define F_IN    512
#define F_HID   256
#define N_CLASS 41
#define H2P     48                            // padded h2 row (bf16)
#define SCAN_BLOCKS ((N_NODES + 255) / 256)   // 391
#define AK 40   // smem k-stride in bf16 halves (32 data + 8 pad)

// ---------------- scratch (device globals; no allocation allowed) ----------
__device__ __nv_bfloat16 g_xb [(size_t)N_NODES * F_IN];    // x in bf16
__device__ __nv_bfloat16 g_w1t[(size_t)F_HID * F_IN];      // W1^T [n][k] bf16
__device__ __nv_bfloat16 g_w2t[(size_t)64 * F_HID];        // W2^T padded [64][256]
__device__ __nv_bfloat16 g_h1b[(size_t)N_NODES * F_HID];   // x@W1 bf16
__device__ __nv_bfloat16 g_a1b[(size_t)N_NODES * F_HID];   // relu(agg+self+b1) bf16
__device__ __nv_bfloat16 g_h2b[(size_t)N_NODES * H2P];     // a1 @ W2 (bf16, padded)
__device__ int   g_deg[N_NODES];
__device__ float g_dinv[N_NODES];
__device__ int   g_rowptr[N_NODES + 1];
__device__ int   g_cursor[N_NODES];
__device__ int   g_bsum[SCAN_BLOCKS];
__device__ int   g_bsumx[SCAN_BLOCKS];
__device__ int   g_csrc[N_EDGES];
__device__ int   g_is64;

// ---------------- small helpers --------------------------------------------
__device__ __forceinline__ void cp16(void* s, const void* g) {
    unsigned sa = (unsigned)__cvta_generic_to_shared(s);
    asm volatile("cp.async.cg.shared.global [%0],[%1],16;" :: "r"(sa), "l"(g));
}
__device__ __forceinline__ void cp16z(void* s, const void* g, bool pred) {
    unsigned sa = (unsigned)__cvta_generic_to_shared(s);
    int sz = pred ? 16 : 0;
    asm volatile("cp.async.cg.shared.global [%0],[%1],16,%2;" :: "r"(sa), "l"(g), "r"(sz));
}
#define CP_COMMIT() asm volatile("cp.async.commit_group;")

__device__ __forceinline__ void mma16816(float c[4], const unsigned a[4],
                                         unsigned b0, unsigned b1) {
    asm volatile(
        "mma.sync.aligned.m16n8k16.row.col.f32.bf16.bf16.f32 "
        "{%0,%1,%2,%3},{%4,%5,%6,%7},{%8,%9},{%0,%1,%2,%3};"
        : "+f"(c[0]), "+f"(c[1]), "+f"(c[2]), "+f"(c[3])
        : "r"(a[0]), "r"(a[1]), "r"(a[2]), "r"(a[3]), "r"(b0), "r"(b1));
}

// ---------------- edge dtype detection -------------------------------------
__global__ void k_detect(const void* __restrict__ ei) {
    if (threadIdx.x == 0 && blockIdx.x == 0) {
        const long long* p = (const long long*)ei;
        int ok = 1;
        for (int e = 0; e < 128; e++) {
            long long v = p[e];
            if (v < 0 || v >= N_NODES) { ok = 0; break; }
        }
        g_is64 = ok;
    }
}

__device__ __forceinline__ void load_edge(const void* __restrict__ ei, int e,
                                          int is64, int& s, int& d) {
    if (is64) {
        const long long* p = (const long long*)ei;
        s = (int)p[e];
        d = (int)p[N_EDGES + e];
    } else {
        const int* p = (const int*)ei;
        s = p[e];
        d = p[N_EDGES + e];
    }
}

// ---------------- degree / dinv --------------------------------------------
__global__ void k_deg_init() {
    int i = blockIdx.x * blockDim.x + threadIdx.x;
    if (i < N_NODES) g_deg[i] = 1;
}
__global__ void k_count(const void* __restrict__ ei) {
    int e = blockIdx.x * blockDim.x + threadIdx.x;
    if (e >= N_EDGES) return;
    int s, d;
    load_edge(ei, e, g_is64, s, d);
    if ((unsigned)d < N_NODES) atomicAdd(&g_deg[d], 1);
}
__global__ void k_dinv() {
    int i = blockIdx.x * blockDim.x + threadIdx.x;
    if (i < N_NODES) g_dinv[i] = rsqrtf((float)g_deg[i]);
}

// ---------------- CSR build -------------------------------------------------
__global__ void k_scan1() {
    __shared__ int sh[256];
    int t = threadIdx.x;
    int i = blockIdx.x * 256 + t;
    int v = (i < N_NODES) ? (g_deg[i] - 1) : 0;
    sh[t] = v;
    __syncthreads();
#pragma unroll
    for (int off = 1; off < 256; off <<= 1) {
        int add = (t >= off) ? sh[t - off] : 0;
        __syncthreads();
        sh[t] += add;
        __syncthreads();
    }
    if (i < N_NODES) g_rowptr[i] = sh[t] - v;
    if (t == 255) g_bsum[blockIdx.x] = sh[t];
}
__global__ void k_scan2() {
    __shared__ int sh[512];
    int t = threadIdx.x;
    int v = (t < SCAN_BLOCKS) ? g_bsum[t] : 0;
    sh[t] = v;
    __syncthreads();
#pragma unroll
    for (int off = 1; off < 512; off <<= 1) {
        int add = (t >= off) ? sh[t - off] : 0;
        __syncthreads();
        sh[t] += add;
        __syncthreads();
    }
    if (t < SCAN_BLOCKS) g_bsumx[t] = sh[t] - v;
}
__global__ void k_scan3() {
    int i = blockIdx.x * blockDim.x + threadIdx.x;
    if (i < N_NODES) {
        int r = g_rowptr[i] + g_bsumx[i >> 8];
        g_rowptr[i] = r;
        g_cursor[i] = r;
    }
}
__global__ void k_fill_total() {
    if (threadIdx.x == 0 && blockIdx.x == 0)
        g_rowptr[N_NODES] = g_bsumx[SCAN_BLOCKS - 1] + g_bsum[SCAN_BLOCKS - 1];
}
__global__ void k_fill(const void* __restrict__ ei) {
    int e = blockIdx.x * blockDim.x + threadIdx.x;
    if (e >= N_EDGES) return;
    int s, d;
    load_edge(ei, e, g_is64, s, d);
    if ((unsigned)s >= N_NODES || (unsigned)d >= N_NODES) return;
    int pos = atomicAdd(&g_cursor[d], 1);
    g_csrc[pos] = s;
}

// ---------------- conversions ----------------------------------------------
__global__ void k_xtobf16(const float* __restrict__ x) {
    size_t i = ((size_t)blockIdx.x * blockDim.x + threadIdx.x) * 8;
    if (i >= (size_t)N_NODES * F_IN) return;
    float4 v0 = *(const float4*)(x + i);
    float4 v1 = *(const float4*)(x + i + 4);
    __nv_bfloat162 p[4];
    p[0] = __floats2bfloat162_rn(v0.x, v0.y);
    p[1] = __floats2bfloat162_rn(v0.z, v0.w);
    p[2] = __floats2bfloat162_rn(v1.x, v1.y);
    p[3] = __floats2bfloat162_rn(v1.z, v1.w);
    *(uint4*)(g_xb + i) = *(uint4*)p;
}
__global__ void k_w1t(const float* __restrict__ W1) {
    int id = blockIdx.x * blockDim.x + threadIdx.x;
    if (id >= F_IN * F_HID) return;
    int n = id & (F_HID - 1), k = id >> 8;
    g_w1t[(size_t)n * F_IN + k] = __float2bfloat16(W1[(size_t)k * F_HID + n]);
}
__global__ void k_w2t(const float* __restrict__ W2) {
    int id = blockIdx.x * blockDim.x + threadIdx.x;
    if (id >= 64 * F_HID) return;
    int n = id & 63, k = id >> 6;
    float v = (n < N_CLASS) ? W2[(size_t)k * N_CLASS + n] : 0.f;
    g_w2t[(size_t)n * F_HID + k] = __float2bfloat16(v);
}

// ---------------- GEMM1: h1b = xb @ W1 (bf16 mma, 128x128 tile) ------------
__global__ __launch_bounds__(256) void k_gemm1t() {
    __shared__ __align__(16) __nv_bfloat16 As[2][128 * AK];
    __shared__ __align__(16) __nv_bfloat16 Bs[2][128 * AK];
    int tid = threadIdx.x;
    int bm = blockIdx.y * 128, bn = blockIdx.x * 128;
    int wid = tid >> 5, lane = tid & 31;
    int wm = (wid & 3) * 32, wn = (wid >> 2) * 64;
    int g = lane >> 2, tg = lane & 3;

    float acc[2][8][4] = {};

#define G1_ISSUE(buf, k0)                                                     \
    {                                                                         \
        _Pragma("unroll")                                                     \
        for (int h = 0; h < 2; h++) {                                         \
            int id = tid + h * 256;                                           \
            int row = id >> 2, kg = id & 3;                                   \
            int ar = bm + row;                                                \
            bool ok = ar < N_NODES;                                           \
            const void* ga = g_xb + (size_t)(ok ? ar : 0) * F_IN + (k0) + kg * 8; \
            cp16z(&As[buf][row * AK + kg * 8], ga, ok);                       \
            const void* gb = g_w1t + (size_t)(bn + row) * F_IN + (k0) + kg * 8; \
            cp16(&Bs[buf][row * AK + kg * 8], gb);                            \
        }                                                                     \
        CP_COMMIT();                                                          \
    }

    G1_ISSUE(0, 0)
    const int nchunk = F_IN / 32;   // 16
    for (int c = 0; c < nchunk; c++) {
        if (c + 1 < nchunk) {
            G1_ISSUE((c + 1) & 1, (c + 1) * 32)
            asm volatile("cp.async.wait_group 1;");
        } else {
            asm volatile("cp.async.wait_group 0;");
        }
        __syncthreads();
        const __nv_bfloat16* A = As[c & 1];
        const __nv_bfloat16* B = Bs[c & 1];
#pragma unroll
        for (int kk = 0; kk < 32; kk += 16) {
            unsigned a[2][4];
#pragma unroll
            for (int mt = 0; mt < 2; mt++) {
                int r = wm + mt * 16 + g;
                a[mt][0] = *(const unsigned*)&A[r * AK + kk + 2 * tg];
                a[mt][1] = *(const unsigned*)&A[(r + 8) * AK + kk + 2 * tg];
                a[mt][2] = *(const unsigned*)&A[r * AK + kk + 2 * tg + 8];
                a[mt][3] = *(const unsigned*)&A[(r + 8) * AK + kk + 2 * tg + 8];
            }
#pragma unroll
            for (int nt = 0; nt < 8; nt++) {
                int n = wn + nt * 8 + g;
                unsigned b0 = *(const unsigned*)&B[n * AK + kk + 2 * tg];
                unsigned b1 = *(const unsigned*)&B[n * AK + kk + 2 * tg + 8];
                mma16816(acc[0][nt], a[0], b0, b1);
                mma16816(acc[1][nt], a[1], b0, b1);
            }
        }
        __syncthreads();
    }
#pragma unroll
    for (int mt = 0; mt < 2; mt++) {
        int r0 = bm + wm + mt * 16 + g;
#pragma unroll
        for (int nt = 0; nt < 8; nt++) {
            int c0 = bn + wn + nt * 8 + 2 * tg;
            if (r0 < N_NODES) {
                __nv_bfloat162 p = __floats2bfloat162_rn(acc[mt][nt][0], acc[mt][nt][1]);
                *(__nv_bfloat162*)&g_h1b[(size_t)r0 * F_HID + c0] = p;
            }
            if (r0 + 8 < N_NODES) {
                __nv_bfloat162 p = __floats2bfloat162_rn(acc[mt][nt][2], acc[mt][nt][3]);
                *(__nv_bfloat162*)&g_h1b[(size_t)(r0 + 8) * F_HID + c0] = p;
            }
        }
    }
}

// ---------------- layer-1 aggregation: CSR gather on bf16 ------------------
__device__ __forceinline__ void acc8(float* acc, uint4 v, float nrm) {
    __nv_bfloat162* h = (__nv_bfloat162*)&v;
    float2 f0 = __bfloat1622float2(h[0]);
    float2 f1 = __bfloat1622float2(h[1]);
    float2 f2 = __bfloat1622float2(h[2]);
    float2 f3 = __bfloat1622float2(h[3]);
    acc[0] += nrm * f0.x; acc[1] += nrm * f0.y;
    acc[2] += nrm * f1.x; acc[3] += nrm * f1.y;
    acc[4] += nrm * f2.x; acc[5] += nrm * f2.y;
    acc[6] += nrm * f3.x; acc[7] += nrm * f3.y;
}

__global__ __launch_bounds__(256) void k_agg1(const float* __restrict__ b1) {
    int node = (blockIdx.x * blockDim.x + threadIdx.x) >> 5;
    int lane = threadIdx.x & 31;
    if (node >= N_NODES) return;
    int beg = g_rowptr[node], end = g_rowptr[node + 1];
    float dinv_d = g_dinv[node];
    const uint4* hb = (const uint4*)g_h1b;   // 32 uint4 per row

    float acc[8] = {};
    int e = beg;
    for (; e + 2 <= end; e += 2) {
        int s0 = g_csrc[e], s1 = g_csrc[e + 1];
        float n0 = g_dinv[s0] * dinv_d, n1 = g_dinv[s1] * dinv_d;
        uint4 v0 = hb[(size_t)s0 * 32 + lane];
        uint4 v1 = hb[(size_t)s1 * 32 + lane];
        acc8(acc, v0, n0);
        acc8(acc, v1, n1);
    }
    if (e < end) {
        int s0 = g_csrc[e];
        uint4 v = hb[(size_t)s0 * 32 + lane];
        acc8(acc, v, g_dinv[s0] * dinv_d);
    }
    {   // self loop
        uint4 v = hb[(size_t)node * 32 + lane];
        acc8(acc, v, dinv_d * dinv_d);
    }
    float4 bv0 = *((const float4*)b1 + lane * 2);
    float4 bv1 = *((const float4*)b1 + lane * 2 + 1);
    float r[8];
    r[0] = fmaxf(acc[0] + bv0.x, 0.f); r[1] = fmaxf(acc[1] + bv0.y, 0.f);
    r[2] = fmaxf(acc[2] + bv0.z, 0.f); r[3] = fmaxf(acc[3] + bv0.w, 0.f);
    r[4] = fmaxf(acc[4] + bv1.x, 0.f); r[5] = fmaxf(acc[5] + bv1.y, 0.f);
    r[6] = fmaxf(acc[6] + bv1.z, 0.f); r[7] = fmaxf(acc[7] + bv1.w, 0.f);
    __nv_bfloat162 p[4];
    p[0] = __floats2bfloat162_rn(r[0], r[1]);
    p[1] = __floats2bfloat162_rn(r[2], r[3]);
    p[2] = __floats2bfloat162_rn(r[4], r[5]);
    p[3] = __floats2bfloat162_rn(r[6], r[7]);
    ((uint4*)g_a1b)[(size_t)node * 32 + lane] = *(uint4*)p;
}

// ---------------- GEMM2: h2b = a1b @ W2 (bf16 mma, 128x64 tile) ------------
__global__ __launch_bounds__(256) void k_gemm2t() {
    __shared__ __align__(16) __nv_bfloat16 As[2][128 * AK];
    __shared__ __align__(16) __nv_bfloat16 Bs[2][64 * AK];
    int tid = threadIdx.x;
    int bm = blockIdx.x * 128;
    int wid = tid >> 5, lane = tid & 31;
    int wm = (wid & 3) * 32, wn = (wid >> 2) * 32;
    int g = lane >> 2, tg = lane & 3;

    float acc[2][4][4] = {};

#define G2_ISSUE(buf, k0)                                                     \
    {                                                                         \
        _Pragma("unroll")                                                     \
        for (int h = 0; h < 2; h++) {                                         \
            int id = tid + h * 256;                                           \
            int row = id >> 2, kg = id & 3;                                   \
            int ar = bm + row;                                                \
            bool ok = ar < N_NODES;                                           \
            const void* ga = g_a1b + (size_t)(ok ? ar : 0) * F_HID + (k0) + kg * 8; \
            cp16z(&As[buf][row * AK + kg * 8], ga, ok);                       \
        }                                                                     \
        {                                                                     \
            int row = tid >> 2, kg = tid & 3;                                 \
            if (row < 64) {                                                   \
                const void* gb = g_w2t + (size_t)row * F_HID + (k0) + kg * 8; \
                cp16(&Bs[buf][row * AK + kg * 8], gb);                        \
            }                                                                 \
        }                                                                     \
        CP_COMMIT();                                                          \
    }

    G2_ISSUE(0, 0)
    const int nchunk = F_HID / 32;   // 8
    for (int c = 0; c < nchunk; c++) {
        if (c + 1 < nchunk) {
            G2_ISSUE((c + 1) & 1, (c + 1) * 32)
            asm volatile("cp.async.wait_group 1;");
        } else {
            asm volatile("cp.async.wait_group 0;");
        }
        __syncthreads();
        const __nv_bfloat16* A = As[c & 1];
        const __nv_bfloat16* B = Bs[c & 1];
#pragma unroll
        for (int kk = 0; kk < 32; kk += 16) {
            unsigned a[2][4];
#pragma unroll
            for (int mt = 0; mt < 2; mt++) {
                int r = wm + mt * 16 + g;
                a[mt][0] = *(const unsigned*)&A[r * AK + kk + 2 * tg];
                a[mt][1] = *(const unsigned*)&A[(r + 8) * AK + kk + 2 * tg];
                a[mt][2] = *(const unsigned*)&A[r * AK + kk + 2 * tg + 8];
                a[mt][3] = *(const unsigned*)&A[(r + 8) * AK + kk + 2 * tg + 8];
            }
#pragma unroll
            for (int nt = 0; nt < 4; nt++) {
                int n = wn + nt * 8 + g;
                unsigned b0 = *(const unsigned*)&B[n * AK + kk + 2 * tg];
                unsigned b1 = *(const unsigned*)&B[n * AK + kk + 2 * tg + 8];
                mma16816(acc[0][nt], a[0], b0, b1);
                mma16816(acc[1][nt], a[1], b0, b1);
            }
        }
        __syncthreads();
    }
#pragma unroll
    for (int mt = 0; mt < 2; mt++) {
        int r0 = bm + wm + mt * 16 + g;
#pragma unroll
        for (int nt = 0; nt < 4; nt++) {
            int c0 = wn + nt * 8 + 2 * tg;
            if (c0 < H2P) {
                if (r0 < N_NODES) {
                    __nv_bfloat162 p = __floats2bfloat162_rn(acc[mt][nt][0], acc[mt][nt][1]);
                    *(__nv_bfloat162*)&g_h2b[(size_t)r0 * H2P + c0] = p;
                }
                if (r0 + 8 < N_NODES) {
                    __nv_bfloat162 p = __floats2bfloat162_rn(acc[mt][nt][2], acc[mt][nt][3]);
                    *(__nv_bfloat162*)&g_h2b[(size_t)(r0 + 8) * H2P + c0] = p;
                }
            }
        }
    }
}

// ---------------- layer-2 aggregation + log_softmax (bf16 gathers) ---------
__global__ __launch_bounds__(256) void k_agg2final(const float* __restrict__ b2,
                                                   float* __restrict__ out) {
    int node = (blockIdx.x * blockDim.x + threadIdx.x) >> 5;
    int lane = threadIdx.x & 31;
    if (node >= N_NODES) return;
    int beg = g_rowptr[node], end = g_rowptr[node + 1];
    float dinv_d = g_dinv[node];
    bool act = lane < 21;                 // lanes carrying classes 2l, 2l+1
    int c0 = lane * 2, c1 = lane * 2 + 1;

    float acc0 = 0.f, acc1 = 0.f;
    for (int e = beg; e < end; e++) {
        int s = g_csrc[e];
        float nrm = g_dinv[s] * dinv_d;
        if (act) {
            __nv_bfloat162 v = *(const __nv_bfloat162*)&g_h2b[(size_t)s * H2P + c0];
            float2 f = __bfloat1622float2(v);
            acc0 += nrm * f.x;
            acc1 += nrm * f.y;
        }
    }
    {   // self loop
        float ds = dinv_d * dinv_d;
        if (act) {
            __nv_bfloat162 v = *(const __nv_bfloat162*)&g_h2b[(size_t)node * H2P + c0];
            float2 f = __bfloat1622float2(v);
            acc0 += ds * f.x;
            acc1 += ds * f.y;
        }
    }
    float v0 = act ? acc0 + b2[c0] : -1e30f;               // c0 <= 40
    float v1 = (lane < 20) ? acc1 + b2[c1] : -1e30f;       // c1 <= 39; lane20 c1=41 pad
    float m = fmaxf(v0, v1);
#pragma unroll
    for (int o = 16; o; o >>= 1) m = fmaxf(m, __shfl_xor_sync(0xffffffffu, m, o));
    float e2 = 0.f;
    if (act) e2 += expf(v0 - m);
    if (lane < 20) e2 += expf(v1 - m);
#pragma unroll
    for (int o = 16; o; o >>= 1) e2 += __shfl_xor_sync(0xffffffffu, e2, o);
    float ls = m + logf(e2);
    size_t base = (size_t)node * N_CLASS;
    if (act) out[base + c0] = v0 - ls;
    if (lane < 20) out[base + c1] = v1 - ls;
}

// ---------------------------------------------------------------------------
extern "C" void kernel_launch(void* const* d_in, const int* in_sizes, int n_in,
                              void* d_out, int out_size) {
    const float* x  = (const float*)d_in[0];
    const void*  ei = d_in[1];
    const float* W1 = (const float*)d_in[2];
    const float* b1 = (const float*)d_in[3];
    const float* W2 = (const float*)d_in[4];
    const float* b2 = (const float*)d_in[5];
    float* out = (float*)d_out;

    // Side stream + events for overlapping the edge chain with the feature
    // chain. Created once (host-side resources, not device memory).
    static cudaStream_t s_side = nullptr;
    static cudaEvent_t  e_fork = nullptr, e_join = nullptr;
    if (!s_side) {
        cudaStreamCreateWithFlags(&s_side, cudaStreamNonBlocking);
        cudaEventCreateWithFlags(&e_fork, cudaEventDisableTiming);
        cudaEventCreateWithFlags(&e_join, cudaEventDisableTiming);
    }

    // Fork: side stream joins the capture via this event.
    cudaEventRecord(e_fork, 0);
    cudaStreamWaitEvent(s_side, e_fork, 0);

    // ---- edge chain (side stream) ----
    k_detect<<<1, 32, 0, s_side>>>(ei);
    k_deg_init<<<(N_NODES + 255) / 256, 256, 0, s_side>>>();
    k_count<<<(N_EDGES + 255) / 256, 256, 0, s_side>>>(ei);
    k_dinv<<<(N_NODES + 255) / 256, 256, 0, s_side>>>();
    k_scan1<<<SCAN_BLOCKS, 256, 0, s_side>>>();
    k_scan2<<<1, 512, 0, s_side>>>();
    k_scan3<<<(N_NODES + 255) / 256, 256, 0, s_side>>>();
    k_fill_total<<<1, 32, 0, s_side>>>();
    k_fill<<<(N_EDGES + 255) / 256, 256, 0, s_side>>>(ei);
    cudaEventRecord(e_join, s_side);

    // ---- feature chain (main stream) ----
    k_xtobf16<<<(int)(((size_t)N_NODES * F_IN / 8 + 255) / 256), 256>>>(x);
    k_w1t<<<(F_IN * F_HID + 255) / 256, 256>>>(W1);
    k_w2t<<<(64 * F_HID + 255) / 256, 256>>>(W2);

    dim3 g1(F_HID / 128, (N_NODES + 127) / 128);   // (2, 782)
    k_gemm1t<<<g1, 256>>>();

    // Join: aggregation needs CSR + dinv from the side stream.
    cudaStreamWaitEvent(0, e_join, 0);

    k_agg1<<<(N_NODES * 32 + 255) / 256, 256>>>(b1);
    k_gemm2t<<<(N_NODES + 127) / 128, 256>>>();
    k_agg2final<<<(N_NODES * 32 + 255) / 256, 256>>>(b2, out);
}

// round 6
// speedup vs baseline: 6.7909x; 1.0704x over previous
#include <cuda_runtime.h>
#include <cuda_bf16.h>

#define N_NODES 100000
#define N_EDGES 3200000
#define F_IN    512
#define F_HID   256
#define N_CLASS 41
#define H2P     48                            // padded h2 row (bf16)
#define SCAN_BLOCKS ((N_NODES + 255) / 256)   // 391
#define AK 40   // smem k-stride in bf16 halves (32 data + 8 pad)

// ---------------- scratch (device globals; no allocation allowed) ----------
__device__ __nv_bfloat16 g_w1t[(size_t)F_HID * F_IN];      // W1^T [n][k] bf16
__device__ __nv_bfloat16 g_w2t[(size_t)64 * F_HID];        // W2^T padded [64][256]
__device__ __nv_bfloat16 g_h1b[(size_t)N_NODES * F_HID];   // x@W1 bf16
__device__ __nv_bfloat16 g_a1b[(size_t)N_NODES * F_HID];   // relu(agg+self+b1) bf16
__device__ __nv_bfloat16 g_h2b[(size_t)N_NODES * H2P];     // a1 @ W2 (bf16, padded)
__device__ int   g_deg[N_NODES];
__device__ float g_dinv[N_NODES];
__device__ int   g_rowptr[N_NODES + 1];
__device__ int   g_cursor[N_NODES];
__device__ int   g_bsum[SCAN_BLOCKS];
__device__ int   g_bsumx[SCAN_BLOCKS];
__device__ int   g_csrc[N_EDGES];
__device__ int   g_is64;

// ---------------- small helpers --------------------------------------------
__device__ __forceinline__ void cp16(void* s, const void* g) {
    unsigned sa = (unsigned)__cvta_generic_to_shared(s);
    asm volatile("cp.async.cg.shared.global [%0],[%1],16;" :: "r"(sa), "l"(g));
}
__device__ __forceinline__ void cp16z(void* s, const void* g, bool pred) {
    unsigned sa = (unsigned)__cvta_generic_to_shared(s);
    int sz = pred ? 16 : 0;
    asm volatile("cp.async.cg.shared.global [%0],[%1],16,%2;" :: "r"(sa), "l"(g), "r"(sz));
}
#define CP_COMMIT() asm volatile("cp.async.commit_group;")

__device__ __forceinline__ void mma16816(float c[4], const unsigned a[4],
                                         unsigned b0, unsigned b1) {
    asm volatile(
        "mma.sync.aligned.m16n8k16.row.col.f32.bf16.bf16.f32 "
        "{%0,%1,%2,%3},{%4,%5,%6,%7},{%8,%9},{%0,%1,%2,%3};"
        : "+f"(c[0]), "+f"(c[1]), "+f"(c[2]), "+f"(c[3])
        : "r"(a[0]), "r"(a[1]), "r"(a[2]), "r"(a[3]), "r"(b0), "r"(b1));
}

// ---------------- edge dtype detection -------------------------------------
__global__ void k_detect(const void* __restrict__ ei) {
    if (threadIdx.x == 0 && blockIdx.x == 0) {
        const long long* p = (const long long*)ei;
        int ok = 1;
        for (int e = 0; e < 128; e++) {
            long long v = p[e];
            if (v < 0 || v >= N_NODES) { ok = 0; break; }
        }
        g_is64 = ok;
    }
}

__device__ __forceinline__ void load_edge(const void* __restrict__ ei, int e,
                                          int is64, int& s, int& d) {
    if (is64) {
        const long long* p = (const long long*)ei;
        s = (int)p[e];
        d = (int)p[N_EDGES + e];
    } else {
        const int* p = (const int*)ei;
        s = p[e];
        d = p[N_EDGES + e];
    }
}

// ---------------- degree / dinv --------------------------------------------
__global__ void k_deg_init() {
    int i = blockIdx.x * blockDim.x + threadIdx.x;
    if (i < N_NODES) g_deg[i] = 1;
}
__global__ void k_count(const void* __restrict__ ei) {
    int e = blockIdx.x * blockDim.x + threadIdx.x;
    if (e >= N_EDGES) return;
    int s, d;
    load_edge(ei, e, g_is64, s, d);
    if ((unsigned)d < N_NODES) atomicAdd(&g_deg[d], 1);
}
__global__ void k_dinv() {
    int i = blockIdx.x * blockDim.x + threadIdx.x;
    if (i < N_NODES) g_dinv[i] = rsqrtf((float)g_deg[i]);
}

// ---------------- CSR build -------------------------------------------------
__global__ void k_scan1() {
    __shared__ int sh[256];
    int t = threadIdx.x;
    int i = blockIdx.x * 256 + t;
    int v = (i < N_NODES) ? (g_deg[i] - 1) : 0;
    sh[t] = v;
    __syncthreads();
#pragma unroll
    for (int off = 1; off < 256; off <<= 1) {
        int add = (t >= off) ? sh[t - off] : 0;
        __syncthreads();
        sh[t] += add;
        __syncthreads();
    }
    if (i < N_NODES) g_rowptr[i] = sh[t] - v;
    if (t == 255) g_bsum[blockIdx.x] = sh[t];
}
__global__ void k_scan2() {
    __shared__ int sh[512];
    int t = threadIdx.x;
    int v = (t < SCAN_BLOCKS) ? g_bsum[t] : 0;
    sh[t] = v;
    __syncthreads();
#pragma unroll
    for (int off = 1; off < 512; off <<= 1) {
        int add = (t >= off) ? sh[t - off] : 0;
        __syncthreads();
        sh[t] += add;
        __syncthreads();
    }
    if (t < SCAN_BLOCKS) g_bsumx[t] = sh[t] - v;
}
__global__ void k_scan3() {
    int i = blockIdx.x * blockDim.x + threadIdx.x;
    if (i < N_NODES) {
        int r = g_rowptr[i] + g_bsumx[i >> 8];
        g_rowptr[i] = r;
        g_cursor[i] = r;
    }
}
__global__ void k_fill_total() {
    if (threadIdx.x == 0 && blockIdx.x == 0)
        g_rowptr[N_NODES] = g_bsumx[SCAN_BLOCKS - 1] + g_bsum[SCAN_BLOCKS - 1];
}
__global__ void k_fill(const void* __restrict__ ei) {
    int e = blockIdx.x * blockDim.x + threadIdx.x;
    if (e >= N_EDGES) return;
    int s, d;
    load_edge(ei, e, g_is64, s, d);
    if ((unsigned)s >= N_NODES || (unsigned)d >= N_NODES) return;
    int pos = atomicAdd(&g_cursor[d], 1);
    g_csrc[pos] = s;
}

// ---------------- weight conversions ---------------------------------------
__global__ void k_w1t(const float* __restrict__ W1) {
    int id = blockIdx.x * blockDim.x + threadIdx.x;
    if (id >= F_IN * F_HID) return;
    int n = id & (F_HID - 1), k = id >> 8;
    g_w1t[(size_t)n * F_IN + k] = __float2bfloat16(W1[(size_t)k * F_HID + n]);
}
__global__ void k_w2t(const float* __restrict__ W2) {
    int id = blockIdx.x * blockDim.x + threadIdx.x;
    if (id >= 64 * F_HID) return;
    int n = id & 63, k = id >> 6;
    float v = (n < N_CLASS) ? W2[(size_t)k * N_CLASS + n] : 0.f;
    g_w2t[(size_t)n * F_HID + k] = __float2bfloat16(v);
}

// ---------------- GEMM1: h1b = x @ W1, fused fp32->bf16 --------------------
// 128x256 tile (full F_HID per CTA, x read once), 512 threads, dynamic smem.
// A: LDG fp32 -> convert -> STS bf16 (register double-buffer).
// B: cp.async bf16 from g_w1t (smem double-buffer).
__global__ __launch_bounds__(512, 1) void k_gemm1f(const float* __restrict__ x) {
    extern __shared__ __align__(16) __nv_bfloat16 smem[];
    __nv_bfloat16* As = smem;                  // 2 bufs x 128*AK
    __nv_bfloat16* Bs = smem + 2 * 128 * AK;   // 2 bufs x 256*AK
    int tid = threadIdx.x;
    int bm = blockIdx.x * 128;
    int wid = tid >> 5, lane = tid & 31;
    int wm = (wid & 3) * 32, wn = (wid >> 2) * 64;
    int g = lane >> 2, tg = lane & 3;

    int arow = tid >> 2;            // 0..127
    int akg  = (tid & 3) * 8;       // 0,8,16,24 (halves)
    bool aok = (bm + arow) < N_NODES;
    const float* abase = x + (size_t)(aok ? bm + arow : 0) * F_IN + akg;

    float acc[2][8][4] = {};
    float4 pf0, pf1;                // prefetched fp32 A chunk

    // ---- preload chunk 0 ----
    pf0 = aok ? *(const float4*)(abase)     : make_float4(0.f, 0.f, 0.f, 0.f);
    pf1 = aok ? *(const float4*)(abase + 4) : make_float4(0.f, 0.f, 0.f, 0.f);
#pragma unroll
    for (int h = 0; h < 2; h++) {            // B chunk 0
        int id = tid + h * 512;
        int row = id >> 2, kg = (id & 3) * 8;
        cp16(&Bs[0 * 256 * AK + row * AK + kg], g_w1t + (size_t)row * F_IN + kg);
    }
    CP_COMMIT();

    const int nchunk = F_IN / 32;   // 16
    for (int c = 0; c < nchunk; c++) {
        int buf = c & 1;
        // STS chunk c (from prefetched regs)
        {
            __nv_bfloat162 p[4];
            p[0] = __floats2bfloat162_rn(pf0.x, pf0.y);
            p[1] = __floats2bfloat162_rn(pf0.z, pf0.w);
            p[2] = __floats2bfloat162_rn(pf1.x, pf1.y);
            p[3] = __floats2bfloat162_rn(pf1.z, pf1.w);
            *(uint4*)&As[buf * 128 * AK + arow * AK + akg] = *(uint4*)p;
        }
        // prefetch chunk c+1
        if (c + 1 < nchunk) {
            int k0 = (c + 1) * 32;
            pf0 = aok ? *(const float4*)(abase + k0)     : make_float4(0.f, 0.f, 0.f, 0.f);
            pf1 = aok ? *(const float4*)(abase + k0 + 4) : make_float4(0.f, 0.f, 0.f, 0.f);
#pragma unroll
            for (int h = 0; h < 2; h++) {
                int id = tid + h * 512;
                int row = id >> 2, kg = (id & 3) * 8;
                cp16(&Bs[(1 - buf) * 256 * AK + row * AK + kg],
                     g_w1t + (size_t)row * F_IN + k0 + kg);
            }
            CP_COMMIT();
            asm volatile("cp.async.wait_group 1;");
        } else {
            asm volatile("cp.async.wait_group 0;");
        }
        __syncthreads();
        const __nv_bfloat16* A = As + buf * 128 * AK;
        const __nv_bfloat16* B = Bs + buf * 256 * AK;
#pragma unroll
        for (int kk = 0; kk < 32; kk += 16) {
            unsigned a[2][4];
#pragma unroll
            for (int mt = 0; mt < 2; mt++) {
                int r = wm + mt * 16 + g;
                a[mt][0] = *(const unsigned*)&A[r * AK + kk + 2 * tg];
                a[mt][1] = *(const unsigned*)&A[(r + 8) * AK + kk + 2 * tg];
                a[mt][2] = *(const unsigned*)&A[r * AK + kk + 2 * tg + 8];
                a[mt][3] = *(const unsigned*)&A[(r + 8) * AK + kk + 2 * tg + 8];
            }
#pragma unroll
            for (int nt = 0; nt < 8; nt++) {
                int n = wn + nt * 8 + g;
                unsigned b0 = *(const unsigned*)&B[n * AK + kk + 2 * tg];
                unsigned b1 = *(const unsigned*)&B[n * AK + kk + 2 * tg + 8];
                mma16816(acc[0][nt], a[0], b0, b1);
                mma16816(acc[1][nt], a[1], b0, b1);
            }
        }
        __syncthreads();
    }
#pragma unroll
    for (int mt = 0; mt < 2; mt++) {
        int r0 = bm + wm + mt * 16 + g;
#pragma unroll
        for (int nt = 0; nt < 8; nt++) {
            int c0 = wn + nt * 8 + 2 * tg;
            if (r0 < N_NODES) {
                __nv_bfloat162 p = __floats2bfloat162_rn(acc[mt][nt][0], acc[mt][nt][1]);
                *(__nv_bfloat162*)&g_h1b[(size_t)r0 * F_HID + c0] = p;
            }
            if (r0 + 8 < N_NODES) {
                __nv_bfloat162 p = __floats2bfloat162_rn(acc[mt][nt][2], acc[mt][nt][3]);
                *(__nv_bfloat162*)&g_h1b[(size_t)(r0 + 8) * F_HID + c0] = p;
            }
        }
    }
}
#define G1_SMEM ((2 * 128 + 2 * 256) * AK * (int)sizeof(__nv_bfloat16))

// ---------------- layer-1 aggregation: CSR gather on bf16 ------------------
__device__ __forceinline__ void acc8(float* acc, uint4 v, float nrm) {
    __nv_bfloat162* h = (__nv_bfloat162*)&v;
    float2 f0 = __bfloat1622float2(h[0]);
    float2 f1 = __bfloat1622float2(h[1]);
    float2 f2 = __bfloat1622float2(h[2]);
    float2 f3 = __bfloat1622float2(h[3]);
    acc[0] += nrm * f0.x; acc[1] += nrm * f0.y;
    acc[2] += nrm * f1.x; acc[3] += nrm * f1.y;
    acc[4] += nrm * f2.x; acc[5] += nrm * f2.y;
    acc[6] += nrm * f3.x; acc[7] += nrm * f3.y;
}

__global__ __launch_bounds__(256) void k_agg1(const float* __restrict__ b1) {
    int node = (blockIdx.x * blockDim.x + threadIdx.x) >> 5;
    int lane = threadIdx.x & 31;
    if (node >= N_NODES) return;
    int beg = g_rowptr[node], end = g_rowptr[node + 1];
    float dinv_d = g_dinv[node];
    const uint4* hb = (const uint4*)g_h1b;

    float acc[8] = {};
    int e = beg;
    for (; e + 2 <= end; e += 2) {
        int s0 = g_csrc[e], s1 = g_csrc[e + 1];
        float n0 = g_dinv[s0] * dinv_d, n1 = g_dinv[s1] * dinv_d;
        uint4 v0 = hb[(size_t)s0 * 32 + lane];
        uint4 v1 = hb[(size_t)s1 * 32 + lane];
        acc8(acc, v0, n0);
        acc8(acc, v1, n1);
    }
    if (e < end) {
        int s0 = g_csrc[e];
        uint4 v = hb[(size_t)s0 * 32 + lane];
        acc8(acc, v, g_dinv[s0] * dinv_d);
    }
    {   // self loop
        uint4 v = hb[(size_t)node * 32 + lane];
        acc8(acc, v, dinv_d * dinv_d);
    }
    float4 bv0 = *((const float4*)b1 + lane * 2);
    float4 bv1 = *((const float4*)b1 + lane * 2 + 1);
    float r[8];
    r[0] = fmaxf(acc[0] + bv0.x, 0.f); r[1] = fmaxf(acc[1] + bv0.y, 0.f);
    r[2] = fmaxf(acc[2] + bv0.z, 0.f); r[3] = fmaxf(acc[3] + bv0.w, 0.f);
    r[4] = fmaxf(acc[4] + bv1.x, 0.f); r[5] = fmaxf(acc[5] + bv1.y, 0.f);
    r[6] = fmaxf(acc[6] + bv1.z, 0.f); r[7] = fmaxf(acc[7] + bv1.w, 0.f);
    __nv_bfloat162 p[4];
    p[0] = __floats2bfloat162_rn(r[0], r[1]);
    p[1] = __floats2bfloat162_rn(r[2], r[3]);
    p[2] = __floats2bfloat162_rn(r[4], r[5]);
    p[3] = __floats2bfloat162_rn(r[6], r[7]);
    ((uint4*)g_a1b)[(size_t)node * 32 + lane] = *(uint4*)p;
}

// ---------------- GEMM2: h2b = a1b @ W2 (bf16 mma, 128x64 tile) ------------
__global__ __launch_bounds__(256) void k_gemm2t() {
    __shared__ __align__(16) __nv_bfloat16 As[2][128 * AK];
    __shared__ __align__(16) __nv_bfloat16 Bs[2][64 * AK];
    int tid = threadIdx.x;
    int bm = blockIdx.x * 128;
    int wid = tid >> 5, lane = tid & 31;
    int wm = (wid & 3) * 32, wn = (wid >> 2) * 32;
    int g = lane >> 2, tg = lane & 3;

    float acc[2][4][4] = {};

#define G2_ISSUE(buf, k0)                                                     \
    {                                                                         \
        _Pragma("unroll")                                                     \
        for (int h = 0; h < 2; h++) {                                         \
            int id = tid + h * 256;                                           \
            int row = id >> 2, kg = id & 3;                                   \
            int ar = bm + row;                                                \
            bool ok = ar < N_NODES;                                           \
            const void* ga = g_a1b + (size_t)(ok ? ar : 0) * F_HID + (k0) + kg * 8; \
            cp16z(&As[buf][row * AK + kg * 8], ga, ok);                       \
        }                                                                     \
        {                                                                     \
            int row = tid >> 2, kg = tid & 3;                                 \
            if (row < 64) {                                                   \
                const void* gb = g_w2t + (size_t)row * F_HID + (k0) + kg * 8; \
                cp16(&Bs[buf][row * AK + kg * 8], gb);                        \
            }                                                                 \
        }                                                                     \
        CP_COMMIT();                                                          \
    }

    G2_ISSUE(0, 0)
    const int nchunk = F_HID / 32;   // 8
    for (int c = 0; c < nchunk; c++) {
        if (c + 1 < nchunk) {
            G2_ISSUE((c + 1) & 1, (c + 1) * 32)
            asm volatile("cp.async.wait_group 1;");
        } else {
            asm volatile("cp.async.wait_group 0;");
        }
        __syncthreads();
        const __nv_bfloat16* A = As[c & 1];
        const __nv_bfloat16* B = Bs[c & 1];
#pragma unroll
        for (int kk = 0; kk < 32; kk += 16) {
            unsigned a[2][4];
#pragma unroll
            for (int mt = 0; mt < 2; mt++) {
                int r = wm + mt * 16 + g;
                a[mt][0] = *(const unsigned*)&A[r * AK + kk + 2 * tg];
                a[mt][1] = *(const unsigned*)&A[(r + 8) * AK + kk + 2 * tg];
                a[mt][2] = *(const unsigned*)&A[r * AK + kk + 2 * tg + 8];
                a[mt][3] = *(const unsigned*)&A[(r + 8) * AK + kk + 2 * tg + 8];
            }
#pragma unroll
            for (int nt = 0; nt < 4; nt++) {
                int n = wn + nt * 8 + g;
                unsigned b0 = *(const unsigned*)&B[n * AK + kk + 2 * tg];
                unsigned b1 = *(const unsigned*)&B[n * AK + kk + 2 * tg + 8];
                mma16816(acc[0][nt], a[0], b0, b1);
                mma16816(acc[1][nt], a[1], b0, b1);
            }
        }
        __syncthreads();
    }
#pragma unroll
    for (int mt = 0; mt < 2; mt++) {
        int r0 = bm + wm + mt * 16 + g;
#pragma unroll
        for (int nt = 0; nt < 4; nt++) {
            int c0 = wn + nt * 8 + 2 * tg;
            if (c0 < H2P) {
                if (r0 < N_NODES) {
                    __nv_bfloat162 p = __floats2bfloat162_rn(acc[mt][nt][0], acc[mt][nt][1]);
                    *(__nv_bfloat162*)&g_h2b[(size_t)r0 * H2P + c0] = p;
                }
                if (r0 + 8 < N_NODES) {
                    __nv_bfloat162 p = __floats2bfloat162_rn(acc[mt][nt][2], acc[mt][nt][3]);
                    *(__nv_bfloat162*)&g_h2b[(size_t)(r0 + 8) * H2P + c0] = p;
                }
            }
        }
    }
}

// ---------------- layer-2 aggregation + log_softmax (bf16 gathers) ---------
__global__ __launch_bounds__(256) void k_agg2final(const float* __restrict__ b2,
                                                   float* __restrict__ out) {
    int node = (blockIdx.x * blockDim.x + threadIdx.x) >> 5;
    int lane = threadIdx.x & 31;
    if (node >= N_NODES) return;
    int beg = g_rowptr[node], end = g_rowptr[node + 1];
    float dinv_d = g_dinv[node];
    bool act = lane < 21;
    int c0 = lane * 2, c1 = lane * 2 + 1;

    float acc0 = 0.f, acc1 = 0.f;
    for (int e = beg; e < end; e++) {
        int s = g_csrc[e];
        float nrm = g_dinv[s] * dinv_d;
        if (act) {
            __nv_bfloat162 v = *(const __nv_bfloat162*)&g_h2b[(size_t)s * H2P + c0];
            float2 f = __bfloat1622float2(v);
            acc0 += nrm * f.x;
            acc1 += nrm * f.y;
        }
    }
    {
        float ds = dinv_d * dinv_d;
        if (act) {
            __nv_bfloat162 v = *(const __nv_bfloat162*)&g_h2b[(size_t)node * H2P + c0];
            float2 f = __bfloat1622float2(v);
            acc0 += ds * f.x;
            acc1 += ds * f.y;
        }
    }
    float v0 = act ? acc0 + b2[c0] : -1e30f;
    float v1 = (lane < 20) ? acc1 + b2[c1] : -1e30f;
    float m = fmaxf(v0, v1);
#pragma unroll
    for (int o = 16; o; o >>= 1) m = fmaxf(m, __shfl_xor_sync(0xffffffffu, m, o));
    float e2 = 0.f;
    if (act) e2 += expf(v0 - m);
    if (lane < 20) e2 += expf(v1 - m);
#pragma unroll
    for (int o = 16; o; o >>= 1) e2 += __shfl_xor_sync(0xffffffffu, e2, o);
    float ls = m + logf(e2);
    size_t base = (size_t)node * N_CLASS;
    if (act) out[base + c0] = v0 - ls;
    if (lane < 20) out[base + c1] = v1 - ls;
}

// ---------------------------------------------------------------------------
extern "C" void kernel_launch(void* const* d_in, const int* in_sizes, int n_in,
                              void* d_out, int out_size) {
    const float* x  = (const float*)d_in[0];
    const void*  ei = d_in[1];
    const float* W1 = (const float*)d_in[2];
    const float* b1 = (const float*)d_in[3];
    const float* W2 = (const float*)d_in[4];
    const float* b2 = (const float*)d_in[5];
    float* out = (float*)d_out;

    static cudaStream_t s_side = nullptr;
    static cudaEvent_t  e_fork = nullptr, e_join = nullptr;
    if (!s_side) {
        cudaStreamCreateWithFlags(&s_side, cudaStreamNonBlocking);
        cudaEventCreateWithFlags(&e_fork, cudaEventDisableTiming);
        cudaEventCreateWithFlags(&e_join, cudaEventDisableTiming);
    }
    // idempotent attribute set (host-side, not an allocation)
    cudaFuncSetAttribute(k_gemm1f, cudaFuncAttributeMaxDynamicSharedMemorySize,
                         G1_SMEM);

    cudaEventRecord(e_fork, 0);
    cudaStreamWaitEvent(s_side, e_fork, 0);

    // ---- edge chain (side stream) ----
    k_detect<<<1, 32, 0, s_side>>>(ei);
    k_deg_init<<<(N_NODES + 255) / 256, 256, 0, s_side>>>();
    k_count<<<(N_EDGES + 255) / 256, 256, 0, s_side>>>(ei);
    k_dinv<<<(N_NODES + 255) / 256, 256, 0, s_side>>>();
    k_scan1<<<SCAN_BLOCKS, 256, 0, s_side>>>();
    k_scan2<<<1, 512, 0, s_side>>>();
    k_scan3<<<(N_NODES + 255) / 256, 256, 0, s_side>>>();
    k_fill_total<<<1, 32, 0, s_side>>>();
    k_fill<<<(N_EDGES + 255) / 256, 256, 0, s_side>>>(ei);
    cudaEventRecord(e_join, s_side);

    // ---- feature chain (main stream) ----
    k_w1t<<<(F_IN * F_HID + 255) / 256, 256>>>(W1);
    k_w2t<<<(64 * F_HID + 255) / 256, 256>>>(W2);
    k_gemm1f<<<(N_NODES + 127) / 128, 512, G1_SMEM>>>(x);

    cudaStreamWaitEvent(0, e_join, 0);

    k_agg1<<<(N_NODES * 32 + 255) / 256, 256>>>(b1);
    k_gemm2t<<<(N_NODES + 127) / 128, 256>>>();
    k_agg2final<<<(N_NODES * 32 + 255) / 256, 256>>>(b2, out);
}